// round 1
// baseline (speedup 1.0000x reference)
#include <cuda_runtime.h>

#define D_MODEL 1024
#define NUM_HEADS 16
#define HEAD_DIM 64
#define SEQ 2048
#define BATCH 2
#define NROWS (BATCH * SEQ)   // 4096

// Scratch (allocation-free rule: __device__ globals)
__device__ float g_Q[(size_t)NROWS * D_MODEL];    // [B][H][S][Dh], scale folded in
__device__ float g_K[(size_t)NROWS * D_MODEL];    // [B][H][S][Dh]
__device__ float g_V[(size_t)NROWS * D_MODEL];    // [B][H][S][Dh]
__device__ float g_ctx[(size_t)NROWS * D_MODEL];  // [B][S][H][Dh] == [4096][1024]

// ---------------------------------------------------------------------------
// Shared SGEMM core: C[128x128] tile of A[M,K] * W[N,K]^T, K = 1024.
// 256 threads, each computes an 8x8 register tile (rows/cols split 4+4 to
// keep smem float4 reads at 2-way conflicts max).
// ---------------------------------------------------------------------------
__device__ __forceinline__ void sgemm128_core(
    const float* __restrict__ A, const float* __restrict__ W,
    int m0, int n0,
    float (*As)[132], float (*Bs)[132],
    float acc[8][8])
{
    const int tid = threadIdx.x;
    const int tx = tid & 15;
    const int ty = tid >> 4;
    const int lrow = tid >> 2;          // 0..63
    const int lcol = (tid & 3) << 2;    // 0,4,8,12

    #pragma unroll
    for (int i = 0; i < 8; i++)
        #pragma unroll
        for (int j = 0; j < 8; j++) acc[i][j] = 0.f;

    for (int k0 = 0; k0 < D_MODEL; k0 += 16) {
        #pragma unroll
        for (int p = 0; p < 2; p++) {
            int r = lrow + p * 64;
            float4 a = *(const float4*)(A + (size_t)(m0 + r) * D_MODEL + k0 + lcol);
            As[lcol + 0][r] = a.x; As[lcol + 1][r] = a.y;
            As[lcol + 2][r] = a.z; As[lcol + 3][r] = a.w;
            float4 b = *(const float4*)(W + (size_t)(n0 + r) * D_MODEL + k0 + lcol);
            Bs[lcol + 0][r] = b.x; Bs[lcol + 1][r] = b.y;
            Bs[lcol + 2][r] = b.z; Bs[lcol + 3][r] = b.w;
        }
        __syncthreads();
        #pragma unroll 4
        for (int k = 0; k < 16; k++) {
            float ar[8], br[8];
            *(float4*)&ar[0] = *(const float4*)&As[k][ty * 4];
            *(float4*)&ar[4] = *(const float4*)&As[k][64 + ty * 4];
            *(float4*)&br[0] = *(const float4*)&Bs[k][tx * 4];
            *(float4*)&br[4] = *(const float4*)&Bs[k][64 + tx * 4];
            #pragma unroll
            for (int i = 0; i < 8; i++)
                #pragma unroll
                for (int j = 0; j < 8; j++)
                    acc[i][j] = fmaf(ar[i], br[j], acc[i][j]);
        }
        __syncthreads();
    }
}

__device__ __forceinline__ int row_of(int ty, int i) {
    return (i < 4) ? (ty * 4 + i) : (64 + ty * 4 + (i - 4));
}

// ---------------------------------------------------------------------------
// QKV projections. z = 0: Q = y*Wq^T (scaled by 1/8), 1: K = x*Wk^T, 2: V.
// Output scattered into [B][H][S][Dh].
// ---------------------------------------------------------------------------
__global__ __launch_bounds__(256, 2)
void qkv_kernel(const float* __restrict__ x, const float* __restrict__ y,
                const float* __restrict__ Wq, const float* __restrict__ Wk,
                const float* __restrict__ Wv)
{
    __shared__ float As[16][132];
    __shared__ float Bs[16][132];

    const int which = blockIdx.z;
    const float* A = (which == 0) ? y : x;
    const float* W = (which == 0) ? Wq : (which == 1) ? Wk : Wv;
    float* Out = (which == 0) ? g_Q : (which == 1) ? g_K : g_V;
    const float scale = (which == 0) ? 0.125f : 1.0f;

    const int tid = threadIdx.x;
    const int tx = tid & 15;
    const int ty = tid >> 4;
    const int m0 = blockIdx.y * 128;
    const int n0 = blockIdx.x * 128;

    float acc[8][8];
    sgemm128_core(A, W, m0, n0, As, Bs, acc);

    #pragma unroll
    for (int i = 0; i < 8; i++) {
        int m = m0 + row_of(ty, i);
        int b = m >> 11, s = m & (SEQ - 1);
        #pragma unroll
        for (int j = 0; j < 8; j++) {
            int n = n0 + row_of(tx, j);
            int h = n >> 6, d = n & (HEAD_DIM - 1);
            Out[(((size_t)b * NUM_HEADS + h) * SEQ + s) * HEAD_DIM + d] = acc[i][j] * scale;
        }
    }
}

// ---------------------------------------------------------------------------
// Output projection: out = ctx * Wo^T, row-major [4096][1024].
// ---------------------------------------------------------------------------
__global__ __launch_bounds__(256, 2)
void proj_kernel(const float* __restrict__ Wo, float* __restrict__ out)
{
    __shared__ float As[16][132];
    __shared__ float Bs[16][132];

    const int tid = threadIdx.x;
    const int tx = tid & 15;
    const int ty = tid >> 4;
    const int m0 = blockIdx.y * 128;
    const int n0 = blockIdx.x * 128;

    float acc[8][8];
    sgemm128_core(g_ctx, Wo, m0, n0, As, Bs, acc);

    #pragma unroll
    for (int i = 0; i < 8; i++) {
        int m = m0 + row_of(ty, i);
        #pragma unroll
        for (int j = 0; j < 8; j++) {
            int n = n0 + row_of(tx, j);
            out[(size_t)m * D_MODEL + n] = acc[i][j];
        }
    }
}

// ---------------------------------------------------------------------------
// Attention: per (b,h), 64-row Q tile, stream KV in 64-wide chunks.
// Naive softmax (plain exp, running row-sum, normalize at the end) — faithful
// to the reference, which does no max-subtraction. Mask added before exp.
// ---------------------------------------------------------------------------
__global__ __launch_bounds__(256)
void attn_kernel(const float* __restrict__ mask)
{
    extern __shared__ float sm[];
    float* sQ  = sm;                   // [64][68]  q-major
    float* sKT = sm + 64 * 68;         // [64][68]  d-major (transposed K)
    float* sV  = sKT + 64 * 68;        // [64][68]  kv-major
    float* sP  = sV + 64 * 68;         // [64][68]  q-major
    float* rowsum = sP + 64 * 68;      // [64]

    const int tid = threadIdx.x;
    const int tx = tid & 15, ty = tid >> 4;
    const int bh = blockIdx.y;                 // 0..31
    const int b = bh >> 4, h = bh & 15;
    const int q0 = blockIdx.x * 64;

    const float* Qb = g_Q + ((size_t)b * NUM_HEADS + h) * SEQ * HEAD_DIM;
    const float* Kb = g_K + ((size_t)b * NUM_HEADS + h) * SEQ * HEAD_DIM;
    const float* Vb = g_V + ((size_t)b * NUM_HEADS + h) * SEQ * HEAD_DIM;

    const int lrow = tid >> 2;          // 0..63
    const int c0   = (tid & 3) << 2;    // 0,4,8,12

    // Load Q tile [64][64]
    #pragma unroll
    for (int p = 0; p < 4; p++) {
        int c = c0 + p * 16;
        *(float4*)&sQ[lrow * 68 + c] =
            *(const float4*)(Qb + (size_t)(q0 + lrow) * HEAD_DIM + c);
    }
    if (tid < 64) rowsum[tid] = 0.f;

    float o[4][4];
    #pragma unroll
    for (int i = 0; i < 4; i++)
        #pragma unroll
        for (int j = 0; j < 4; j++) o[i][j] = 0.f;

    for (int kv0 = 0; kv0 < SEQ; kv0 += 64) {
        __syncthreads();   // previous PV / rowsum reads of sP, sV done
        // Load K chunk transposed, V chunk direct
        #pragma unroll
        for (int p = 0; p < 4; p++) {
            int c = c0 + p * 16;
            float4 kvv = *(const float4*)(Kb + (size_t)(kv0 + lrow) * HEAD_DIM + c);
            sKT[(c + 0) * 68 + lrow] = kvv.x;
            sKT[(c + 1) * 68 + lrow] = kvv.y;
            sKT[(c + 2) * 68 + lrow] = kvv.z;
            sKT[(c + 3) * 68 + lrow] = kvv.w;
            *(float4*)&sV[lrow * 68 + c] =
                *(const float4*)(Vb + (size_t)(kv0 + lrow) * HEAD_DIM + c);
        }
        __syncthreads();

        // S = Q * K^T  (scale already folded into Q)
        float acc[4][4];
        #pragma unroll
        for (int i = 0; i < 4; i++)
            #pragma unroll
            for (int j = 0; j < 4; j++) acc[i][j] = 0.f;

        #pragma unroll 8
        for (int d = 0; d < 64; d++) {
            float aq[4], bk[4];
            #pragma unroll
            for (int i = 0; i < 4; i++) aq[i] = sQ[(ty * 4 + i) * 68 + d];
            *(float4*)bk = *(const float4*)&sKT[d * 68 + tx * 4];
            #pragma unroll
            for (int i = 0; i < 4; i++)
                #pragma unroll
                for (int j = 0; j < 4; j++)
                    acc[i][j] = fmaf(aq[i], bk[j], acc[i][j]);
        }

        // mask + exp, stash P in smem
        #pragma unroll
        for (int i = 0; i < 4; i++) {
            int qg = q0 + ty * 4 + i;
            #pragma unroll
            for (int j = 0; j < 4; j++) {
                int kg = kv0 + tx * 4 + j;
                acc[i][j] = __expf(acc[i][j] + mask[(size_t)qg * SEQ + kg]);
            }
            *(float4*)&sP[(ty * 4 + i) * 68 + tx * 4] = *(float4*)&acc[i][0];
        }
        __syncthreads();

        // Row-sum accumulation (threads 0..63)
        if (tid < 64) {
            float rs = 0.f;
            #pragma unroll 8
            for (int k = 0; k < 64; k++) rs += sP[tid * 68 + k];
            rowsum[tid] += rs;
        }

        // O += P * V
        #pragma unroll 8
        for (int kv = 0; kv < 64; kv++) {
            float ap[4], bv[4];
            #pragma unroll
            for (int i = 0; i < 4; i++) ap[i] = sP[(ty * 4 + i) * 68 + kv];
            *(float4*)bv = *(const float4*)&sV[kv * 68 + tx * 4];
            #pragma unroll
            for (int i = 0; i < 4; i++)
                #pragma unroll
                for (int j = 0; j < 4; j++)
                    o[i][j] = fmaf(ap[i], bv[j], o[i][j]);
        }
    }
    __syncthreads();

    // Normalize, write ctx as [B][S][H][Dh]
    #pragma unroll
    for (int i = 0; i < 4; i++) {
        int qr = ty * 4 + i;
        float inv = 1.f / (rowsum[qr] + 1e-10f);
        int s = q0 + qr;
        #pragma unroll
        for (int j = 0; j < 4; j++) {
            int d = tx * 4 + j;
            g_ctx[(((size_t)b * SEQ + s) * NUM_HEADS + h) * HEAD_DIM + d] = o[i][j] * inv;
        }
    }
}

// ---------------------------------------------------------------------------
// Launch: metadata order is x, y, mask, Wq, Wk, Wv, Wo; output fp32 [2,2048,1024].
// ---------------------------------------------------------------------------
extern "C" void kernel_launch(void* const* d_in, const int* in_sizes, int n_in,
                              void* d_out, int out_size)
{
    (void)in_sizes; (void)n_in; (void)out_size;
    const float* x    = (const float*)d_in[0];
    const float* y    = (const float*)d_in[1];
    const float* mask = (const float*)d_in[2];
    const float* Wq   = (const float*)d_in[3];
    const float* Wk   = (const float*)d_in[4];
    const float* Wv   = (const float*)d_in[5];
    const float* Wo   = (const float*)d_in[6];
    float* out = (float*)d_out;

    // 1) QKV projections
    dim3 g1(D_MODEL / 128, NROWS / 128, 3);
    qkv_kernel<<<g1, 256>>>(x, y, Wq, Wk, Wv);

    // 2) Attention
    int smem = (4 * 64 * 68 + 64) * (int)sizeof(float);   // 69888 B
    cudaFuncSetAttribute(attn_kernel, cudaFuncAttributeMaxDynamicSharedMemorySize, smem);
    dim3 g2(SEQ / 64, BATCH * NUM_HEADS);
    attn_kernel<<<g2, 256, smem>>>(mask);

    // 3) Output projection
    dim3 g3(D_MODEL / 128, NROWS / 128);
    proj_kernel<<<g3, 256>>>(Wo, out);
}

// round 3
// speedup vs baseline: 1.3091x; 1.3091x over previous
#include <cuda_runtime.h>
#include <cuda_bf16.h>
#include <cstdint>

#define D_MODEL 1024
#define NUM_HEADS 16
#define HEAD_DIM 64
#define SEQ 2048
#define BATCH 2
#define NROWS (BATCH * SEQ)   // 4096
#define KEFF 3072             // split-bf16: [hi|hi|lo] x [hi|lo|hi]
#define KSLAB 64
#define NSLAB (KEFF / KSLAB)  // 48

// ---------------------------------------------------------------------------
// Scratch (__device__ globals; allocation-free rule)
// ---------------------------------------------------------------------------
__device__ float g_Q[(size_t)NROWS * D_MODEL];    // [B][H][S][Dh] (Wq pre-scaled)
__device__ float g_K[(size_t)NROWS * D_MODEL];
__device__ float g_V[(size_t)NROWS * D_MODEL];
__device__ float g_ctx[(size_t)NROWS * D_MODEL];  // [B][S][H][Dh]
__device__ __nv_bfloat16 g_A2x[(size_t)NROWS * KEFF];
__device__ __nv_bfloat16 g_A2y[(size_t)NROWS * KEFF];
__device__ __nv_bfloat16 g_C2[(size_t)NROWS * KEFF];
__device__ __nv_bfloat16 g_W2q[(size_t)D_MODEL * KEFF];
__device__ __nv_bfloat16 g_W2k[(size_t)D_MODEL * KEFF];
__device__ __nv_bfloat16 g_W2v[(size_t)D_MODEL * KEFF];
__device__ __nv_bfloat16 g_W2o[(size_t)D_MODEL * KEFF];

// ---------------------------------------------------------------------------
// Helpers (baseline PTX only: ldmatrix / mma.sync / cp.async)
// ---------------------------------------------------------------------------
__device__ __forceinline__ uint32_t smem_u32(const void* p) {
    uint32_t a;
    asm("{ .reg .u64 t; cvta.to.shared.u64 t, %1; cvt.u32.u64 %0, t; }" : "=r"(a) : "l"(p));
    return a;
}
#define SWZ(o) ((o) ^ (((o) >> 3) & 0x70))

__device__ __forceinline__ void ldsm_x4(uint32_t* r, uint32_t addr) {
    asm volatile("ldmatrix.sync.aligned.m8n8.x4.shared.b16 {%0,%1,%2,%3}, [%4];"
        : "=r"(r[0]), "=r"(r[1]), "=r"(r[2]), "=r"(r[3]) : "r"(addr));
}
__device__ __forceinline__ void mma_bf16(float* c, const uint32_t* a, uint32_t b0, uint32_t b1) {
    asm volatile(
        "mma.sync.aligned.m16n8k16.row.col.f32.bf16.bf16.f32 "
        "{%0,%1,%2,%3}, {%4,%5,%6,%7}, {%8,%9}, {%0,%1,%2,%3};"
        : "+f"(c[0]), "+f"(c[1]), "+f"(c[2]), "+f"(c[3])
        : "r"(a[0]), "r"(a[1]), "r"(a[2]), "r"(a[3]), "r"(b0), "r"(b1));
}
#define CP_ASYNC16(dst, src) \
    asm volatile("cp.async.cg.shared.global [%0], [%1], 16;" :: "r"(dst), "l"(src))
#define CP_COMMIT() asm volatile("cp.async.commit_group;" ::: "memory")
#define CP_WAIT1()  asm volatile("cp.async.wait_group 1;" ::: "memory")
#define CP_WAIT0()  asm volatile("cp.async.wait_group 0;" ::: "memory")

// ---------------------------------------------------------------------------
// Split-bf16 conversion kernels
// ---------------------------------------------------------------------------
__device__ __forceinline__ void split_write(__nv_bfloat16* out, size_t o, float v, int patB) {
    __nv_bfloat16 hi = __float2bfloat16(v);
    __nv_bfloat16 lo = __float2bfloat16(v - __bfloat162float(hi));
    if (patB) { out[o] = hi; out[o + 1024] = lo; out[o + 2048] = hi; }
    else      { out[o] = hi; out[o + 1024] = hi; out[o + 2048] = lo; }
}

__global__ void split_inputs_kernel(const float* __restrict__ x, const float* __restrict__ y) {
    int idx = blockIdx.x * blockDim.x + threadIdx.x;
    const float* in = blockIdx.z ? x : y;
    __nv_bfloat16* out = blockIdx.z ? g_A2x : g_A2y;
    int r = idx >> 10, c = idx & 1023;
    split_write(out, (size_t)r * KEFF + c, in[idx], 0);
}

__global__ void split_w_kernel(const float* __restrict__ Wq, const float* __restrict__ Wk,
                               const float* __restrict__ Wv, const float* __restrict__ Wo) {
    int idx = blockIdx.x * blockDim.x + threadIdx.x;
    const float* in = blockIdx.z == 0 ? Wq : blockIdx.z == 1 ? Wk : blockIdx.z == 2 ? Wv : Wo;
    __nv_bfloat16* out = blockIdx.z == 0 ? g_W2q : blockIdx.z == 1 ? g_W2k
                       : blockIdx.z == 2 ? g_W2v : g_W2o;
    float scale = (blockIdx.z == 0) ? 0.125f : 1.0f;    // fold 1/sqrt(Dh) into Wq
    int r = idx >> 10, c = idx & 1023;
    split_write(out, (size_t)r * KEFF + c, in[idx] * scale, 1);
}

__global__ void split_ctx_kernel() {
    int idx = blockIdx.x * blockDim.x + threadIdx.x;
    int r = idx >> 10, c = idx & 1023;
    split_write(g_C2, (size_t)r * KEFF + c, g_ctx[idx], 0);
}

// ---------------------------------------------------------------------------
// HMMA GEMM: C[128x128] = A2[m0..][KEFF] * B2[n0..][KEFF]^T
// 256 threads = 8 warps (4 M x 2 N); warp tile 32x64 via m16n8k16.
// smem: double-buffered A/B K-slabs of 64 (each 128 rows x 128 B, swizzled).
// ---------------------------------------------------------------------------
#define GSMEM_BYTES (4 * 16384)   // 64 KB

__device__ __forceinline__ void load_slab(const __nv_bfloat16* A, const __nv_bfloat16* Bw,
                                          uint32_t sb, int m0, int n0, int s, int buf) {
    const int tid = threadIdx.x;
    const int k0 = s * KSLAB;
    const uint32_t abase = sb + buf * 32768;
    const uint32_t bbase = abase + 16384;
    #pragma unroll
    for (int t = 0; t < 4; t++) {
        int id = tid + t * 256;
        int r = id >> 3, cb = (id & 7) * 16;
        const char* ga = (const char*)A + ((size_t)(m0 + r) * KEFF + k0) * 2 + cb;
        const char* gb = (const char*)Bw + ((size_t)(n0 + r) * KEFF + k0) * 2 + cb;
        CP_ASYNC16(abase + SWZ(r * 128 + cb), ga);
        CP_ASYNC16(bbase + SWZ(r * 128 + cb), gb);
    }
    CP_COMMIT();
}

__device__ __forceinline__ void gemm_core(const __nv_bfloat16* __restrict__ A,
                                          const __nv_bfloat16* __restrict__ Bw,
                                          float* __restrict__ out, int out_mode) {
    extern __shared__ char smem[];
    const uint32_t sb = smem_u32(smem);
    const int tid = threadIdx.x, lane = tid & 31, warp = tid >> 5;
    const int wm = (warp & 3) * 32;
    const int wn = (warp >> 2) * 64;
    const int m0 = blockIdx.y * 128, n0 = blockIdx.x * 128;

    float acc[2][8][4];
    #pragma unroll
    for (int i = 0; i < 2; i++)
        #pragma unroll
        for (int j = 0; j < 8; j++)
            #pragma unroll
            for (int q = 0; q < 4; q++) acc[i][j][q] = 0.f;

    load_slab(A, Bw, sb, m0, n0, 0, 0);
    load_slab(A, Bw, sb, m0, n0, 1, 1);

    const int lrow = lane & 15;         // row within 16-row ldmatrix group
    const int lk16 = (lane >> 4) * 16;  // +16B for k-high half

    for (int s = 0; s < NSLAB; s++) {
        if (s + 1 < NSLAB) CP_WAIT1(); else CP_WAIT0();
        __syncthreads();
        const uint32_t abase = sb + (s & 1) * 32768;
        const uint32_t bbase = abase + 16384;

        #pragma unroll
        for (int kk = 0; kk < 4; kk++) {
            const int kb = kk * 32;     // byte offset of this k16 within row
            uint32_t a_r[2][4], b_r[4][4];
            #pragma unroll
            for (int mi = 0; mi < 2; mi++)
                ldsm_x4(a_r[mi], abase + SWZ((wm + mi * 16 + lrow) * 128 + kb + lk16));
            #pragma unroll
            for (int nj = 0; nj < 4; nj++)
                ldsm_x4(b_r[nj], bbase + SWZ((wn + nj * 16 + lrow) * 128 + kb + lk16));
            #pragma unroll
            for (int mi = 0; mi < 2; mi++)
                #pragma unroll
                for (int nj = 0; nj < 4; nj++) {
                    mma_bf16(acc[mi][nj * 2],     a_r[mi], b_r[nj][0], b_r[nj][2]);
                    mma_bf16(acc[mi][nj * 2 + 1], a_r[mi], b_r[nj][1], b_r[nj][3]);
                }
        }
        __syncthreads();
        if (s + 2 < NSLAB) load_slab(A, Bw, sb, m0, n0, s + 2, s & 1);
    }

    // Epilogue: c0,c1 -> (row = lane>>2, col = (lane&3)*2 +0/1); c2,c3 -> row+8
    #pragma unroll
    for (int mi = 0; mi < 2; mi++)
        #pragma unroll
        for (int nj = 0; nj < 8; nj++) {
            #pragma unroll
            for (int half = 0; half < 2; half++) {
                int m = m0 + wm + mi * 16 + (lane >> 2) + half * 8;
                int n = n0 + wn + nj * 8 + (lane & 3) * 2;
                float v0 = acc[mi][nj][half * 2], v1 = acc[mi][nj][half * 2 + 1];
                if (out_mode == 1) {
                    out[(size_t)m * D_MODEL + n] = v0;
                    out[(size_t)m * D_MODEL + n + 1] = v1;
                } else {
                    int b = m >> 11, sq = m & (SEQ - 1);
                    int h = n >> 6, d = n & (HEAD_DIM - 1);
                    size_t base = (((size_t)b * NUM_HEADS + h) * SEQ + sq) * HEAD_DIM + d;
                    out[base] = v0;
                    out[base + 1] = v1;   // d+1 < 64 since d is even and 2-aligned within head
                }
            }
        }
}

__global__ __launch_bounds__(256) void gemm_qkv_kernel() {
    const __nv_bfloat16* A = blockIdx.z == 0 ? g_A2y : g_A2x;
    const __nv_bfloat16* Bw = blockIdx.z == 0 ? g_W2q : blockIdx.z == 1 ? g_W2k : g_W2v;
    float* out = blockIdx.z == 0 ? g_Q : blockIdx.z == 1 ? g_K : g_V;
    gemm_core(A, Bw, out, 0);
}

__global__ __launch_bounds__(256) void gemm_proj_kernel(float* __restrict__ out) {
    gemm_core(g_C2, g_W2o, out, 1);
}

// ---------------------------------------------------------------------------
// Attention (fp32 FFMA, unchanged): per (b,h), 64-row Q tile, 64-wide KV
// chunks, naive softmax (plain exp, running row-sum, normalize at end).
// ---------------------------------------------------------------------------
__global__ __launch_bounds__(256)
void attn_kernel(const float* __restrict__ mask)
{
    extern __shared__ float sm[];
    float* sQ  = sm;
    float* sKT = sm + 64 * 68;
    float* sV  = sKT + 64 * 68;
    float* sP  = sV + 64 * 68;
    float* rowsum = sP + 64 * 68;

    const int tid = threadIdx.x;
    const int tx = tid & 15, ty = tid >> 4;
    const int bh = blockIdx.y;
    const int b = bh >> 4, h = bh & 15;
    const int q0 = blockIdx.x * 64;

    const float* Qb = g_Q + ((size_t)b * NUM_HEADS + h) * SEQ * HEAD_DIM;
    const float* Kb = g_K + ((size_t)b * NUM_HEADS + h) * SEQ * HEAD_DIM;
    const float* Vb = g_V + ((size_t)b * NUM_HEADS + h) * SEQ * HEAD_DIM;

    const int lrow = tid >> 2;
    const int c0   = (tid & 3) << 2;

    #pragma unroll
    for (int p = 0; p < 4; p++) {
        int c = c0 + p * 16;
        *(float4*)&sQ[lrow * 68 + c] =
            *(const float4*)(Qb + (size_t)(q0 + lrow) * HEAD_DIM + c);
    }
    if (tid < 64) rowsum[tid] = 0.f;

    float o[4][4];
    #pragma unroll
    for (int i = 0; i < 4; i++)
        #pragma unroll
        for (int j = 0; j < 4; j++) o[i][j] = 0.f;

    for (int kv0 = 0; kv0 < SEQ; kv0 += 64) {
        __syncthreads();
        #pragma unroll
        for (int p = 0; p < 4; p++) {
            int c = c0 + p * 16;
            float4 kvv = *(const float4*)(Kb + (size_t)(kv0 + lrow) * HEAD_DIM + c);
            sKT[(c + 0) * 68 + lrow] = kvv.x;
            sKT[(c + 1) * 68 + lrow] = kvv.y;
            sKT[(c + 2) * 68 + lrow] = kvv.z;
            sKT[(c + 3) * 68 + lrow] = kvv.w;
            *(float4*)&sV[lrow * 68 + c] =
                *(const float4*)(Vb + (size_t)(kv0 + lrow) * HEAD_DIM + c);
        }
        __syncthreads();

        float acc[4][4];
        #pragma unroll
        for (int i = 0; i < 4; i++)
            #pragma unroll
            for (int j = 0; j < 4; j++) acc[i][j] = 0.f;

        #pragma unroll 8
        for (int d = 0; d < 64; d++) {
            float aq[4], bk[4];
            #pragma unroll
            for (int i = 0; i < 4; i++) aq[i] = sQ[(ty * 4 + i) * 68 + d];
            *(float4*)bk = *(const float4*)&sKT[d * 68 + tx * 4];
            #pragma unroll
            for (int i = 0; i < 4; i++)
                #pragma unroll
                for (int j = 0; j < 4; j++)
                    acc[i][j] = fmaf(aq[i], bk[j], acc[i][j]);
        }

        #pragma unroll
        for (int i = 0; i < 4; i++) {
            int qg = q0 + ty * 4 + i;
            #pragma unroll
            for (int j = 0; j < 4; j++) {
                int kg = kv0 + tx * 4 + j;
                acc[i][j] = __expf(acc[i][j] + mask[(size_t)qg * SEQ + kg]);
            }
            *(float4*)&sP[(ty * 4 + i) * 68 + tx * 4] = *(float4*)&acc[i][0];
        }
        __syncthreads();

        if (tid < 64) {
            float rs = 0.f;
            #pragma unroll 8
            for (int k = 0; k < 64; k++) rs += sP[tid * 68 + k];
            rowsum[tid] += rs;
        }

        #pragma unroll 8
        for (int kv = 0; kv < 64; kv++) {
            float ap[4], bv[4];
            #pragma unroll
            for (int i = 0; i < 4; i++) ap[i] = sP[(ty * 4 + i) * 68 + kv];
            *(float4*)bv = *(const float4*)&sV[kv * 68 + tx * 4];
            #pragma unroll
            for (int i = 0; i < 4; i++)
                #pragma unroll
                for (int j = 0; j < 4; j++)
                    o[i][j] = fmaf(ap[i], bv[j], o[i][j]);
        }
    }
    __syncthreads();

    #pragma unroll
    for (int i = 0; i < 4; i++) {
        int qr = ty * 4 + i;
        float inv = 1.f / (rowsum[qr] + 1e-10f);
        int s = q0 + qr;
        #pragma unroll
        for (int j = 0; j < 4; j++) {
            int d = tx * 4 + j;
            g_ctx[(((size_t)b * SEQ + s) * NUM_HEADS + h) * HEAD_DIM + d] = o[i][j] * inv;
        }
    }
}

// ---------------------------------------------------------------------------
// Launch
// ---------------------------------------------------------------------------
extern "C" void kernel_launch(void* const* d_in, const int* in_sizes, int n_in,
                              void* d_out, int out_size)
{
    (void)in_sizes; (void)n_in; (void)out_size;
    const float* x    = (const float*)d_in[0];
    const float* y    = (const float*)d_in[1];
    const float* mask = (const float*)d_in[2];
    const float* Wq   = (const float*)d_in[3];
    const float* Wk   = (const float*)d_in[4];
    const float* Wv   = (const float*)d_in[5];
    const float* Wo   = (const float*)d_in[6];
    float* out = (float*)d_out;

    cudaFuncSetAttribute(gemm_qkv_kernel, cudaFuncAttributeMaxDynamicSharedMemorySize, GSMEM_BYTES);
    cudaFuncSetAttribute(gemm_proj_kernel, cudaFuncAttributeMaxDynamicSharedMemorySize, GSMEM_BYTES);
    int asmem = (4 * 64 * 68 + 64) * (int)sizeof(float);
    cudaFuncSetAttribute(attn_kernel, cudaFuncAttributeMaxDynamicSharedMemorySize, asmem);

    // 1) split conversions
    {
        dim3 g((NROWS * 1024) / 256, 1, 2);
        split_inputs_kernel<<<g, 256>>>(x, y);
        dim3 gw((1024 * 1024) / 256, 1, 4);
        split_w_kernel<<<gw, 256>>>(Wq, Wk, Wv, Wo);
    }

    // 2) QKV projections (HMMA)
    {
        dim3 g(D_MODEL / 128, NROWS / 128, 3);
        gemm_qkv_kernel<<<g, 256, GSMEM_BYTES>>>();
    }

    // 3) Attention (fp32)
    {
        dim3 g(SEQ / 64, BATCH * NUM_HEADS);
        attn_kernel<<<g, 256, asmem>>>(mask);
    }

    // 4) split ctx + output projection (HMMA)
    {
        split_ctx_kernel<<<(NROWS * 1024) / 256, 256>>>();
        dim3 g(D_MODEL / 128, NROWS / 128);
        gemm_proj_kernel<<<g, 256, GSMEM_BYTES>>>(out);
    }
}

// round 4
// speedup vs baseline: 2.2480x; 1.7172x over previous
#include <cuda_runtime.h>
#include <cuda_bf16.h>
#include <cstdint>

#define D_MODEL 1024
#define NUM_HEADS 16
#define HEAD_DIM 64
#define SEQ 2048
#define BATCH 2
#define NROWS (BATCH * SEQ)   // 4096
#define KEFF 3072             // split-bf16: [hi|hi|lo] x [hi|lo|hi]
#define KSLAB 64
#define NSLAB (KEFF / KSLAB)  // 48

// ---------------------------------------------------------------------------
// Scratch (__device__ globals; allocation-free rule)
// ---------------------------------------------------------------------------
__device__ __nv_bfloat16 g_A2x[(size_t)NROWS * KEFF];
__device__ __nv_bfloat16 g_A2y[(size_t)NROWS * KEFF];
__device__ __nv_bfloat16 g_C2[(size_t)NROWS * KEFF];          // split ctx (attn writes)
__device__ __nv_bfloat16 g_W2q[(size_t)D_MODEL * KEFF];
__device__ __nv_bfloat16 g_W2k[(size_t)D_MODEL * KEFF];
__device__ __nv_bfloat16 g_W2v[(size_t)D_MODEL * KEFF];
__device__ __nv_bfloat16 g_W2o[(size_t)D_MODEL * KEFF];
// split Q/K: [B,H,S,Dh]; split V transposed: [B,H,Dh,S]
__device__ __nv_bfloat16 g_Qh[(size_t)NROWS * D_MODEL];
__device__ __nv_bfloat16 g_Ql[(size_t)NROWS * D_MODEL];
__device__ __nv_bfloat16 g_Kh[(size_t)NROWS * D_MODEL];
__device__ __nv_bfloat16 g_Kl[(size_t)NROWS * D_MODEL];
__device__ __nv_bfloat16 g_Vh[(size_t)NROWS * D_MODEL];
__device__ __nv_bfloat16 g_Vl[(size_t)NROWS * D_MODEL];

// ---------------------------------------------------------------------------
// Helpers (baseline PTX only)
// ---------------------------------------------------------------------------
__device__ __forceinline__ uint32_t smem_u32(const void* p) {
    uint32_t a;
    asm("{ .reg .u64 t; cvta.to.shared.u64 t, %1; cvt.u32.u64 %0, t; }" : "=r"(a) : "l"(p));
    return a;
}
#define SWZ(o)    ((o) ^ (((o) >> 3) & 0x70))   // 128B rows
#define SWZ256(o) ((o) ^ (((o) >> 4) & 0x70))   // 256B rows

__device__ __forceinline__ void ldsm_x4(uint32_t* r, uint32_t addr) {
    asm volatile("ldmatrix.sync.aligned.m8n8.x4.shared.b16 {%0,%1,%2,%3}, [%4];"
        : "=r"(r[0]), "=r"(r[1]), "=r"(r[2]), "=r"(r[3]) : "r"(addr));
}
__device__ __forceinline__ void mma_bf16(float* c, const uint32_t* a, uint32_t b0, uint32_t b1) {
    asm volatile(
        "mma.sync.aligned.m16n8k16.row.col.f32.bf16.bf16.f32 "
        "{%0,%1,%2,%3}, {%4,%5,%6,%7}, {%8,%9}, {%0,%1,%2,%3};"
        : "+f"(c[0]), "+f"(c[1]), "+f"(c[2]), "+f"(c[3])
        : "r"(a[0]), "r"(a[1]), "r"(a[2]), "r"(a[3]), "r"(b0), "r"(b1));
}
#define CP_ASYNC16(dst, src) \
    asm volatile("cp.async.cg.shared.global [%0], [%1], 16;" :: "r"(dst), "l"(src))
#define CP_COMMIT() asm volatile("cp.async.commit_group;" ::: "memory")
#define CP_WAIT1()  asm volatile("cp.async.wait_group 1;" ::: "memory")
#define CP_WAIT0()  asm volatile("cp.async.wait_group 0;" ::: "memory")

__device__ __forceinline__ void st_bf2(__nv_bfloat16* p, __nv_bfloat16 a, __nv_bfloat16 b) {
    __nv_bfloat162 t; t.x = a; t.y = b;
    *(__nv_bfloat162*)p = t;
}

// ---------------------------------------------------------------------------
// Split-bf16 conversion kernels (inputs + weights)
// ---------------------------------------------------------------------------
__device__ __forceinline__ void split_write(__nv_bfloat16* out, size_t o, float v, int patB) {
    __nv_bfloat16 hi = __float2bfloat16(v);
    __nv_bfloat16 lo = __float2bfloat16(v - __bfloat162float(hi));
    if (patB) { out[o] = hi; out[o + 1024] = lo; out[o + 2048] = hi; }
    else      { out[o] = hi; out[o + 1024] = hi; out[o + 2048] = lo; }
}

__global__ void split_inputs_kernel(const float* __restrict__ x, const float* __restrict__ y) {
    int idx = blockIdx.x * blockDim.x + threadIdx.x;
    const float* in = blockIdx.z ? x : y;
    __nv_bfloat16* out = blockIdx.z ? g_A2x : g_A2y;
    int r = idx >> 10, c = idx & 1023;
    split_write(out, (size_t)r * KEFF + c, in[idx], 0);
}

__global__ void split_w_kernel(const float* __restrict__ Wq, const float* __restrict__ Wk,
                               const float* __restrict__ Wv, const float* __restrict__ Wo) {
    int idx = blockIdx.x * blockDim.x + threadIdx.x;
    const float* in = blockIdx.z == 0 ? Wq : blockIdx.z == 1 ? Wk : blockIdx.z == 2 ? Wv : Wo;
    __nv_bfloat16* out = blockIdx.z == 0 ? g_W2q : blockIdx.z == 1 ? g_W2k
                       : blockIdx.z == 2 ? g_W2v : g_W2o;
    float scale = (blockIdx.z == 0) ? 0.125f : 1.0f;    // fold 1/sqrt(Dh) into Wq
    int r = idx >> 10, c = idx & 1023;
    split_write(out, (size_t)r * KEFF + c, in[idx] * scale, 1);
}

// ---------------------------------------------------------------------------
// HMMA GEMM: C[128x128] = A2[m0..][KEFF] * B2[n0..][KEFF]^T
// out_mode: 0=Q split [B,H,S,Dh], 1=K split, 2=V split transposed [B,H,Dh,S],
//           3=fp32 row-major (final projection)
// ---------------------------------------------------------------------------
#define GSMEM_BYTES (4 * 16384)

__device__ __forceinline__ void load_slab(const __nv_bfloat16* A, const __nv_bfloat16* Bw,
                                          uint32_t sb, int m0, int n0, int s, int buf) {
    const int tid = threadIdx.x;
    const int k0 = s * KSLAB;
    const uint32_t abase = sb + buf * 32768;
    const uint32_t bbase = abase + 16384;
    #pragma unroll
    for (int t = 0; t < 4; t++) {
        int id = tid + t * 256;
        int r = id >> 3, cb = (id & 7) * 16;
        const char* ga = (const char*)A + ((size_t)(m0 + r) * KEFF + k0) * 2 + cb;
        const char* gb = (const char*)Bw + ((size_t)(n0 + r) * KEFF + k0) * 2 + cb;
        CP_ASYNC16(abase + SWZ(r * 128 + cb), ga);
        CP_ASYNC16(bbase + SWZ(r * 128 + cb), gb);
    }
    CP_COMMIT();
}

__device__ __forceinline__ void gemm_core(const __nv_bfloat16* __restrict__ A,
                                          const __nv_bfloat16* __restrict__ Bw,
                                          float* __restrict__ out, int out_mode) {
    extern __shared__ char smem[];
    const uint32_t sb = smem_u32(smem);
    const int tid = threadIdx.x, lane = tid & 31, warp = tid >> 5;
    const int wm = (warp & 3) * 32;
    const int wn = (warp >> 2) * 64;
    const int m0 = blockIdx.y * 128, n0 = blockIdx.x * 128;

    float acc[2][8][4];
    #pragma unroll
    for (int i = 0; i < 2; i++)
        #pragma unroll
        for (int j = 0; j < 8; j++)
            #pragma unroll
            for (int q = 0; q < 4; q++) acc[i][j][q] = 0.f;

    load_slab(A, Bw, sb, m0, n0, 0, 0);
    load_slab(A, Bw, sb, m0, n0, 1, 1);

    const int lrow = lane & 15;
    const int lk16 = (lane >> 4) * 16;

    for (int s = 0; s < NSLAB; s++) {
        if (s + 1 < NSLAB) CP_WAIT1(); else CP_WAIT0();
        __syncthreads();
        const uint32_t abase = sb + (s & 1) * 32768;
        const uint32_t bbase = abase + 16384;

        #pragma unroll
        for (int kk = 0; kk < 4; kk++) {
            const int kb = kk * 32;
            uint32_t a_r[2][4], b_r[4][4];
            #pragma unroll
            for (int mi = 0; mi < 2; mi++)
                ldsm_x4(a_r[mi], abase + SWZ((wm + mi * 16 + lrow) * 128 + kb + lk16));
            #pragma unroll
            for (int nj = 0; nj < 4; nj++)
                ldsm_x4(b_r[nj], bbase + SWZ((wn + nj * 16 + lrow) * 128 + kb + lk16));
            #pragma unroll
            for (int mi = 0; mi < 2; mi++)
                #pragma unroll
                for (int nj = 0; nj < 4; nj++) {
                    mma_bf16(acc[mi][nj * 2],     a_r[mi], b_r[nj][0], b_r[nj][2]);
                    mma_bf16(acc[mi][nj * 2 + 1], a_r[mi], b_r[nj][1], b_r[nj][3]);
                }
        }
        __syncthreads();
        if (s + 2 < NSLAB) load_slab(A, Bw, sb, m0, n0, s + 2, s & 1);
    }

    #pragma unroll
    for (int mi = 0; mi < 2; mi++)
        #pragma unroll
        for (int nj = 0; nj < 8; nj++) {
            #pragma unroll
            for (int half = 0; half < 2; half++) {
                int m = m0 + wm + mi * 16 + (lane >> 2) + half * 8;
                int n = n0 + wn + nj * 8 + (lane & 3) * 2;
                float v0 = acc[mi][nj][half * 2], v1 = acc[mi][nj][half * 2 + 1];
                if (out_mode == 3) {
                    out[(size_t)m * D_MODEL + n] = v0;
                    out[(size_t)m * D_MODEL + n + 1] = v1;
                } else {
                    int b = m >> 11, sq = m & (SEQ - 1);
                    int h = n >> 6, d = n & (HEAD_DIM - 1);
                    __nv_bfloat16 h0 = __float2bfloat16(v0);
                    __nv_bfloat16 l0 = __float2bfloat16(v0 - __bfloat162float(h0));
                    __nv_bfloat16 h1 = __float2bfloat16(v1);
                    __nv_bfloat16 l1 = __float2bfloat16(v1 - __bfloat162float(h1));
                    if (out_mode == 2) {   // V transposed [B,H,Dh,S]
                        size_t o0 = ((size_t)(b * NUM_HEADS + h) * HEAD_DIM + d) * SEQ + sq;
                        g_Vh[o0] = h0; g_Vl[o0] = l0;
                        g_Vh[o0 + SEQ] = h1; g_Vl[o0 + SEQ] = l1;
                    } else {
                        size_t o = (((size_t)b * NUM_HEADS + h) * SEQ + sq) * HEAD_DIM + d;
                        if (out_mode == 0) { st_bf2(&g_Qh[o], h0, h1); st_bf2(&g_Ql[o], l0, l1); }
                        else               { st_bf2(&g_Kh[o], h0, h1); st_bf2(&g_Kl[o], l0, l1); }
                    }
                }
            }
        }
}

__global__ __launch_bounds__(256) void gemm_qkv_kernel() {
    const __nv_bfloat16* A = blockIdx.z == 0 ? g_A2y : g_A2x;
    const __nv_bfloat16* Bw = blockIdx.z == 0 ? g_W2q : blockIdx.z == 1 ? g_W2k : g_W2v;
    gemm_core(A, Bw, nullptr, (int)blockIdx.z);
}

__global__ __launch_bounds__(256) void gemm_proj_kernel(float* __restrict__ out) {
    gemm_core(g_C2, g_W2o, out, 3);
}

// ---------------------------------------------------------------------------
// HMMA attention. Per CTA: (b,h), 128 q-rows; stream kv in 128-chunks.
// S = 3-term split HMMA; naive softmax (plain exp, global rowsum); P split to
// bf16 hi/lo in smem; PV = 3-term split HMMA accumulated in regs.
// smem: Qh/Ql 16K each | Kh/Kl 16K | Vh/Vl 16K (V^T, 64x256B) | Ph/Pl 32K | rs 1K
// ---------------------------------------------------------------------------
#define oQh 0
#define oQl 16384
#define oKh 32768
#define oKl 49152
#define oVh 65536
#define oVl 81920
#define oPh 98304
#define oPl 131072
#define oRS 163840
#define ASMEM_BYTES (163840 + 1024)

__global__ __launch_bounds__(256, 1)
void attn_hmma_kernel(const float* __restrict__ mask)
{
    extern __shared__ char smem[];
    const uint32_t sb = smem_u32(smem);
    const int tid = threadIdx.x, lane = tid & 31, warp = tid >> 5;
    const int wm = (warp & 3) * 32;        // q offset of warp tile
    const int wn = (warp >> 2) * 64;       // kv offset (S phase)
    const int wn2 = (warp >> 2) * 32;      // d offset (PV phase)
    const int lrow = lane & 15;
    const int lk16 = (lane >> 4) * 16;

    const int bh = blockIdx.y;
    const int b = bh >> 4, h = bh & 15;
    const int q0 = blockIdx.x * 128;

    const char* Qhp = (const char*)g_Qh + (size_t)bh * SEQ * HEAD_DIM * 2;
    const char* Qlp = (const char*)g_Ql + (size_t)bh * SEQ * HEAD_DIM * 2;
    const char* Khp = (const char*)g_Kh + (size_t)bh * SEQ * HEAD_DIM * 2;
    const char* Klp = (const char*)g_Kl + (size_t)bh * SEQ * HEAD_DIM * 2;
    const char* Vhp = (const char*)g_Vh + (size_t)bh * HEAD_DIM * SEQ * 2;
    const char* Vlp = (const char*)g_Vl + (size_t)bh * HEAD_DIM * SEQ * 2;

    // ---- load Q (hi+lo) and K chunk 0 ----
    #pragma unroll
    for (int t = 0; t < 4; t++) {
        int id = tid + t * 256;
        int r = id >> 3, cb = (id & 7) * 16;
        uint32_t so = SWZ(r * 128 + cb);
        CP_ASYNC16(sb + oQh + so, Qhp + (size_t)(q0 + r) * 128 + cb);
        CP_ASYNC16(sb + oQl + so, Qlp + (size_t)(q0 + r) * 128 + cb);
        CP_ASYNC16(sb + oKh + so, Khp + (size_t)r * 128 + cb);
        CP_ASYNC16(sb + oKl + so, Klp + (size_t)r * 128 + cb);
    }
    CP_COMMIT();

    float rs[4] = {0.f, 0.f, 0.f, 0.f};
    float oacc[2][4][4];
    #pragma unroll
    for (int i = 0; i < 2; i++)
        #pragma unroll
        for (int j = 0; j < 4; j++)
            #pragma unroll
            for (int q = 0; q < 4; q++) oacc[i][j][q] = 0.f;

    for (int c = 0; c < SEQ / 128; c++) {
        const int kv0 = c * 128;
        // prefetch V chunk (V^T rows d=0..63, cols kv0..+127; 256B rows)
        #pragma unroll
        for (int t = 0; t < 4; t++) {
            int id = tid + t * 256;
            int r = id >> 4, cb = (id & 15) * 16;
            uint32_t so = SWZ256(r * 256 + cb);
            CP_ASYNC16(sb + oVh + so, Vhp + (size_t)r * (SEQ * 2) + kv0 * 2 + cb);
            CP_ASYNC16(sb + oVl + so, Vlp + (size_t)r * (SEQ * 2) + kv0 * 2 + cb);
        }
        CP_COMMIT();
        CP_WAIT1();           // K chunk (and Q on c==0) ready; V may be in flight
        __syncthreads();

        // ---- S = Q K^T (3-term split) ----
        float sacc[2][8][4];
        #pragma unroll
        for (int i = 0; i < 2; i++)
            #pragma unroll
            for (int j = 0; j < 8; j++)
                #pragma unroll
                for (int q = 0; q < 4; q++) sacc[i][j][q] = 0.f;

        #pragma unroll
        for (int kk = 0; kk < 4; kk++) {
            const int kb = kk * 32;
            uint32_t qh[2][4], ql[2][4];
            #pragma unroll
            for (int mi = 0; mi < 2; mi++) {
                uint32_t ro = SWZ((wm + mi * 16 + lrow) * 128 + kb + lk16);
                ldsm_x4(qh[mi], sb + oQh + ro);
                ldsm_x4(ql[mi], sb + oQl + ro);
            }
            #pragma unroll
            for (int nj = 0; nj < 4; nj++) {
                uint32_t kh[4], kl[4];
                uint32_t ro = SWZ((wn + nj * 16 + lrow) * 128 + kb + lk16);
                ldsm_x4(kh, sb + oKh + ro);
                ldsm_x4(kl, sb + oKl + ro);
                #pragma unroll
                for (int mi = 0; mi < 2; mi++) {
                    mma_bf16(sacc[mi][nj * 2],     qh[mi], kh[0], kh[2]);
                    mma_bf16(sacc[mi][nj * 2 + 1], qh[mi], kh[1], kh[3]);
                    mma_bf16(sacc[mi][nj * 2],     qh[mi], kl[0], kl[2]);
                    mma_bf16(sacc[mi][nj * 2 + 1], qh[mi], kl[1], kl[3]);
                    mma_bf16(sacc[mi][nj * 2],     ql[mi], kh[0], kh[2]);
                    mma_bf16(sacc[mi][nj * 2 + 1], ql[mi], kh[1], kh[3]);
                }
            }
        }

        // ---- softmax: mask + exp, rowsum, split P to smem ----
        #pragma unroll
        for (int mi = 0; mi < 2; mi++)
            #pragma unroll
            for (int nj = 0; nj < 8; nj++)
                #pragma unroll
                for (int half = 0; half < 2; half++) {
                    int rl = wm + mi * 16 + (lane >> 2) + half * 8;
                    int cl = wn + nj * 8 + (lane & 3) * 2;
                    float2 mk = *(const float2*)&mask[(size_t)(q0 + rl) * SEQ + kv0 + cl];
                    float e0 = __expf(sacc[mi][nj][half * 2]     + mk.x);
                    float e1 = __expf(sacc[mi][nj][half * 2 + 1] + mk.y);
                    rs[mi * 2 + half] += e0 + e1;
                    __nv_bfloat16 h0 = __float2bfloat16(e0);
                    __nv_bfloat16 l0 = __float2bfloat16(e0 - __bfloat162float(h0));
                    __nv_bfloat16 h1 = __float2bfloat16(e1);
                    __nv_bfloat16 l1 = __float2bfloat16(e1 - __bfloat162float(h1));
                    uint32_t po = SWZ256(rl * 256 + cl * 2);
                    st_bf2((__nv_bfloat16*)(smem + oPh + po), h0, h1);
                    st_bf2((__nv_bfloat16*)(smem + oPl + po), l0, l1);
                }

        CP_WAIT0();           // V chunk ready
        __syncthreads();      // P fully written, K reads done

        // prefetch next K chunk (overlaps PV)
        if (c + 1 < SEQ / 128) {
            const int kvn = (c + 1) * 128;
            #pragma unroll
            for (int t = 0; t < 4; t++) {
                int id = tid + t * 256;
                int r = id >> 3, cb = (id & 7) * 16;
                uint32_t so = SWZ(r * 128 + cb);
                CP_ASYNC16(sb + oKh + so, Khp + (size_t)(kvn + r) * 128 + cb);
                CP_ASYNC16(sb + oKl + so, Klp + (size_t)(kvn + r) * 128 + cb);
            }
            CP_COMMIT();
        }

        // ---- O += P V (3-term split), k = 128 ----
        #pragma unroll
        for (int kk = 0; kk < 8; kk++) {
            const int kb = kk * 32;
            uint32_t ph[2][4], pl[2][4];
            #pragma unroll
            for (int mi = 0; mi < 2; mi++) {
                uint32_t ro = SWZ256((wm + mi * 16 + lrow) * 256 + kb + lk16);
                ldsm_x4(ph[mi], sb + oPh + ro);
                ldsm_x4(pl[mi], sb + oPl + ro);
            }
            #pragma unroll
            for (int nj = 0; nj < 2; nj++) {
                uint32_t vh[4], vl[4];
                uint32_t ro = SWZ256((wn2 + nj * 16 + lrow) * 256 + kb + lk16);
                ldsm_x4(vh, sb + oVh + ro);
                ldsm_x4(vl, sb + oVl + ro);
                #pragma unroll
                for (int mi = 0; mi < 2; mi++) {
                    mma_bf16(oacc[mi][nj * 2],     ph[mi], vh[0], vh[2]);
                    mma_bf16(oacc[mi][nj * 2 + 1], ph[mi], vh[1], vh[3]);
                    mma_bf16(oacc[mi][nj * 2],     ph[mi], vl[0], vl[2]);
                    mma_bf16(oacc[mi][nj * 2 + 1], ph[mi], vl[1], vl[3]);
                    mma_bf16(oacc[mi][nj * 2],     pl[mi], vh[0], vh[2]);
                    mma_bf16(oacc[mi][nj * 2 + 1], pl[mi], vh[1], vh[3]);
                }
            }
        }
        __syncthreads();      // V/P buffers reusable next chunk
    }

    // ---- rowsum: quad butterfly + cross-warp reduce ----
    #pragma unroll
    for (int i = 0; i < 4; i++) {
        rs[i] += __shfl_xor_sync(0xffffffffu, rs[i], 1);
        rs[i] += __shfl_xor_sync(0xffffffffu, rs[i], 2);
    }
    float* rsm = (float*)(smem + oRS);   // [2][128]
    if ((lane & 3) == 0) {
        #pragma unroll
        for (int mi = 0; mi < 2; mi++)
            #pragma unroll
            for (int half = 0; half < 2; half++)
                rsm[(warp >> 2) * 128 + wm + mi * 16 + (lane >> 2) + half * 8] = rs[mi * 2 + half];
    }
    __syncthreads();

    // ---- normalize + write split ctx into g_C2 [4096][3072] ([hi|hi|lo]) ----
    #pragma unroll
    for (int mi = 0; mi < 2; mi++)
        #pragma unroll
        for (int nj = 0; nj < 4; nj++)
            #pragma unroll
            for (int half = 0; half < 2; half++) {
                int rl = wm + mi * 16 + (lane >> 2) + half * 8;
                float inv = 1.f / (rsm[rl] + rsm[128 + rl] + 1e-10f);
                int sq = q0 + rl;
                int dc = wn2 + nj * 8 + (lane & 3) * 2;
                float v0 = oacc[mi][nj][half * 2] * inv;
                float v1 = oacc[mi][nj][half * 2 + 1] * inv;
                __nv_bfloat16 h0 = __float2bfloat16(v0);
                __nv_bfloat16 l0 = __float2bfloat16(v0 - __bfloat162float(h0));
                __nv_bfloat16 h1 = __float2bfloat16(v1);
                __nv_bfloat16 l1 = __float2bfloat16(v1 - __bfloat162float(h1));
                size_t o = (size_t)(b * SEQ + sq) * KEFF + h * HEAD_DIM + dc;
                st_bf2(&g_C2[o], h0, h1);
                st_bf2(&g_C2[o + 1024], h0, h1);
                st_bf2(&g_C2[o + 2048], l0, l1);
            }
}

// ---------------------------------------------------------------------------
// Launch
// ---------------------------------------------------------------------------
extern "C" void kernel_launch(void* const* d_in, const int* in_sizes, int n_in,
                              void* d_out, int out_size)
{
    (void)in_sizes; (void)n_in; (void)out_size;
    const float* x    = (const float*)d_in[0];
    const float* y    = (const float*)d_in[1];
    const float* mask = (const float*)d_in[2];
    const float* Wq   = (const float*)d_in[3];
    const float* Wk   = (const float*)d_in[4];
    const float* Wv   = (const float*)d_in[5];
    const float* Wo   = (const float*)d_in[6];
    float* out = (float*)d_out;

    cudaFuncSetAttribute(gemm_qkv_kernel, cudaFuncAttributeMaxDynamicSharedMemorySize, GSMEM_BYTES);
    cudaFuncSetAttribute(gemm_proj_kernel, cudaFuncAttributeMaxDynamicSharedMemorySize, GSMEM_BYTES);
    cudaFuncSetAttribute(attn_hmma_kernel, cudaFuncAttributeMaxDynamicSharedMemorySize, ASMEM_BYTES);

    // 1) split conversions
    {
        dim3 g((NROWS * 1024) / 256, 1, 2);
        split_inputs_kernel<<<g, 256>>>(x, y);
        dim3 gw((1024 * 1024) / 256, 1, 4);
        split_w_kernel<<<gw, 256>>>(Wq, Wk, Wv, Wo);
    }
    // 2) QKV projections (HMMA) -> split Q/K/V
    {
        dim3 g(D_MODEL / 128, NROWS / 128, 3);
        gemm_qkv_kernel<<<g, 256, GSMEM_BYTES>>>();
    }
    // 3) Attention (HMMA, split-bf16) -> split ctx
    {
        dim3 g(SEQ / 128, BATCH * NUM_HEADS);
        attn_hmma_kernel<<<g, 256, ASMEM_BYTES>>>(mask);
    }
    // 4) Output projection (HMMA)
    {
        dim3 g(D_MODEL / 128, NROWS / 128);
        gemm_proj_kernel<<<g, 256, GSMEM_BYTES>>>(out);
    }
}

// round 10
// speedup vs baseline: 2.2961x; 1.0214x over previous
#include <cuda_runtime.h>
#include <cuda_bf16.h>
#include <cstdint>

#define D_MODEL 1024
#define NUM_HEADS 16
#define HEAD_DIM 64
#define SEQ 2048
#define BATCH 2
#define NROWS (BATCH * SEQ)   // 4096
#define KEFF 3072             // split-bf16: [hi|hi|lo] x [hi|lo|hi]
#define KSLAB 64
#define NSLAB (KEFF / KSLAB)  // 48

// ---------------------------------------------------------------------------
// Scratch (__device__ globals; allocation-free rule)
// ---------------------------------------------------------------------------
__device__ __nv_bfloat16 g_A2x[(size_t)NROWS * KEFF];
__device__ __nv_bfloat16 g_A2y[(size_t)NROWS * KEFF];
__device__ __nv_bfloat16 g_C2[(size_t)NROWS * KEFF];          // split ctx (attn writes)
__device__ __nv_bfloat16 g_W2q[(size_t)D_MODEL * KEFF];
__device__ __nv_bfloat16 g_W2k[(size_t)D_MODEL * KEFF];
__device__ __nv_bfloat16 g_W2v[(size_t)D_MODEL * KEFF];
__device__ __nv_bfloat16 g_W2o[(size_t)D_MODEL * KEFF];
// split Q/K: [B,H,S,Dh]; split V transposed: [B,H,Dh,S]
__device__ __nv_bfloat16 g_Qh[(size_t)NROWS * D_MODEL];
__device__ __nv_bfloat16 g_Ql[(size_t)NROWS * D_MODEL];
__device__ __nv_bfloat16 g_Kh[(size_t)NROWS * D_MODEL];
__device__ __nv_bfloat16 g_Kl[(size_t)NROWS * D_MODEL];
__device__ __nv_bfloat16 g_Vh[(size_t)NROWS * D_MODEL];
__device__ __nv_bfloat16 g_Vl[(size_t)NROWS * D_MODEL];

// ---------------------------------------------------------------------------
// Helpers (baseline PTX only)
// ---------------------------------------------------------------------------
__device__ __forceinline__ uint32_t smem_u32(const void* p) {
    uint32_t a;
    asm("{ .reg .u64 t; cvta.to.shared.u64 t, %1; cvt.u32.u64 %0, t; }" : "=r"(a) : "l"(p));
    return a;
}
#define SWZ(o)    ((o) ^ (((o) >> 3) & 0x70))   // 128B rows
#define SWZ256(o) ((o) ^ (((o) >> 4) & 0x70))   // 256B rows

__device__ __forceinline__ void ldsm_x4(uint32_t* r, uint32_t addr) {
    asm volatile("ldmatrix.sync.aligned.m8n8.x4.shared.b16 {%0,%1,%2,%3}, [%4];"
        : "=r"(r[0]), "=r"(r[1]), "=r"(r[2]), "=r"(r[3]) : "r"(addr));
}
__device__ __forceinline__ void mma_bf16(float* c, const uint32_t* a, uint32_t b0, uint32_t b1) {
    asm volatile(
        "mma.sync.aligned.m16n8k16.row.col.f32.bf16.bf16.f32 "
        "{%0,%1,%2,%3}, {%4,%5,%6,%7}, {%8,%9}, {%0,%1,%2,%3};"
        : "+f"(c[0]), "+f"(c[1]), "+f"(c[2]), "+f"(c[3])
        : "r"(a[0]), "r"(a[1]), "r"(a[2]), "r"(a[3]), "r"(b0), "r"(b1));
}
#define CP_ASYNC16(dst, src) \
    asm volatile("cp.async.cg.shared.global [%0], [%1], 16;" :: "r"(dst), "l"(src))
#define CP_COMMIT() asm volatile("cp.async.commit_group;" ::: "memory")
#define CP_WAIT1()  asm volatile("cp.async.wait_group 1;" ::: "memory")
#define CP_WAIT0()  asm volatile("cp.async.wait_group 0;" ::: "memory")

__device__ __forceinline__ void st_bf2(__nv_bfloat16* p, __nv_bfloat16 a, __nv_bfloat16 b) {
    __nv_bfloat162 t; t.x = a; t.y = b;
    *(__nv_bfloat162*)p = t;
}

// ---------------------------------------------------------------------------
// Split-bf16 conversion kernels (inputs + weights)
// ---------------------------------------------------------------------------
__device__ __forceinline__ void split_write(__nv_bfloat16* out, size_t o, float v, int patB) {
    __nv_bfloat16 hi = __float2bfloat16(v);
    __nv_bfloat16 lo = __float2bfloat16(v - __bfloat162float(hi));
    if (patB) { out[o] = hi; out[o + 1024] = lo; out[o + 2048] = hi; }
    else      { out[o] = hi; out[o + 1024] = hi; out[o + 2048] = lo; }
}

__global__ void split_inputs_kernel(const float* __restrict__ x, const float* __restrict__ y) {
    int idx = blockIdx.x * blockDim.x + threadIdx.x;
    const float* in = blockIdx.z ? x : y;
    __nv_bfloat16* out = blockIdx.z ? g_A2x : g_A2y;
    int r = idx >> 10, c = idx & 1023;
    split_write(out, (size_t)r * KEFF + c, in[idx], 0);
}

__global__ void split_w_kernel(const float* __restrict__ Wq, const float* __restrict__ Wk,
                               const float* __restrict__ Wv, const float* __restrict__ Wo) {
    int idx = blockIdx.x * blockDim.x + threadIdx.x;
    const float* in = blockIdx.z == 0 ? Wq : blockIdx.z == 1 ? Wk : blockIdx.z == 2 ? Wv : Wo;
    __nv_bfloat16* out = blockIdx.z == 0 ? g_W2q : blockIdx.z == 1 ? g_W2k
                       : blockIdx.z == 2 ? g_W2v : g_W2o;
    float scale = (blockIdx.z == 0) ? 0.125f : 1.0f;    // fold 1/sqrt(Dh) into Wq
    int r = idx >> 10, c = idx & 1023;
    split_write(out, (size_t)r * KEFF + c, in[idx] * scale, 1);
}

// ---------------------------------------------------------------------------
// HMMA GEMM: C[128x128] = A2[m0..][KEFF] * B2[n0..][KEFF]^T, 3-stage pipeline.
// out_mode: 0=Q split, 1=K split, 2=V split transposed, 3=fp32 row-major
// ---------------------------------------------------------------------------
#define GSMEM_BYTES (6 * 16384)   // 3 stages x (A 16K + B 16K)

__device__ __forceinline__ void load_slab(const __nv_bfloat16* A, const __nv_bfloat16* Bw,
                                          uint32_t sb, int m0, int n0, int s, int buf) {
    const int tid = threadIdx.x;
    const int k0 = s * KSLAB;
    const uint32_t abase = sb + buf * 32768;
    const uint32_t bbase = abase + 16384;
    #pragma unroll
    for (int t = 0; t < 4; t++) {
        int id = tid + t * 256;
        int r = id >> 3, cb = (id & 7) * 16;
        const char* ga = (const char*)A + ((size_t)(m0 + r) * KEFF + k0) * 2 + cb;
        const char* gb = (const char*)Bw + ((size_t)(n0 + r) * KEFF + k0) * 2 + cb;
        CP_ASYNC16(abase + SWZ(r * 128 + cb), ga);
        CP_ASYNC16(bbase + SWZ(r * 128 + cb), gb);
    }
    CP_COMMIT();
}

__device__ __forceinline__ void gemm_core(const __nv_bfloat16* __restrict__ A,
                                          const __nv_bfloat16* __restrict__ Bw,
                                          float* __restrict__ out, int out_mode) {
    extern __shared__ char smem[];
    const uint32_t sb = smem_u32(smem);
    const int tid = threadIdx.x, lane = tid & 31, warp = tid >> 5;
    const int wm = (warp & 3) * 32;
    const int wn = (warp >> 2) * 64;
    const int m0 = blockIdx.y * 128, n0 = blockIdx.x * 128;

    float acc[2][8][4];
    #pragma unroll
    for (int i = 0; i < 2; i++)
        #pragma unroll
        for (int j = 0; j < 8; j++)
            #pragma unroll
            for (int q = 0; q < 4; q++) acc[i][j][q] = 0.f;

    load_slab(A, Bw, sb, m0, n0, 0, 0);
    load_slab(A, Bw, sb, m0, n0, 1, 1);

    const int lrow = lane & 15;
    const int lk16 = (lane >> 4) * 16;

    int buf = 0;
    for (int s = 0; s < NSLAB; s++) {
        if (s + 1 < NSLAB) CP_WAIT1(); else CP_WAIT0();
        __syncthreads();
        // issue slab s+2 into the buffer consumed at iteration s-1 (safe after sync)
        if (s + 2 < NSLAB) {
            int nbuf = buf + 2; if (nbuf >= 3) nbuf -= 3;
            load_slab(A, Bw, sb, m0, n0, s + 2, nbuf);
        }
        const uint32_t abase = sb + buf * 32768;
        const uint32_t bbase = abase + 16384;

        #pragma unroll
        for (int kk = 0; kk < 4; kk++) {
            const int kb = kk * 32;
            uint32_t a_r[2][4], b_r[4][4];
            #pragma unroll
            for (int mi = 0; mi < 2; mi++)
                ldsm_x4(a_r[mi], abase + SWZ((wm + mi * 16 + lrow) * 128 + kb + lk16));
            #pragma unroll
            for (int nj = 0; nj < 4; nj++)
                ldsm_x4(b_r[nj], bbase + SWZ((wn + nj * 16 + lrow) * 128 + kb + lk16));
            #pragma unroll
            for (int mi = 0; mi < 2; mi++)
                #pragma unroll
                for (int nj = 0; nj < 4; nj++) {
                    mma_bf16(acc[mi][nj * 2],     a_r[mi], b_r[nj][0], b_r[nj][2]);
                    mma_bf16(acc[mi][nj * 2 + 1], a_r[mi], b_r[nj][1], b_r[nj][3]);
                }
        }
        buf++; if (buf >= 3) buf = 0;
    }

    #pragma unroll
    for (int mi = 0; mi < 2; mi++)
        #pragma unroll
        for (int nj = 0; nj < 8; nj++) {
            #pragma unroll
            for (int half = 0; half < 2; half++) {
                int m = m0 + wm + mi * 16 + (lane >> 2) + half * 8;
                int n = n0 + wn + nj * 8 + (lane & 3) * 2;
                float v0 = acc[mi][nj][half * 2], v1 = acc[mi][nj][half * 2 + 1];
                if (out_mode == 3) {
                    out[(size_t)m * D_MODEL + n] = v0;
                    out[(size_t)m * D_MODEL + n + 1] = v1;
                } else {
                    int b = m >> 11, sq = m & (SEQ - 1);
                    int h = n >> 6, d = n & (HEAD_DIM - 1);
                    __nv_bfloat16 h0 = __float2bfloat16(v0);
                    __nv_bfloat16 l0 = __float2bfloat16(v0 - __bfloat162float(h0));
                    __nv_bfloat16 h1 = __float2bfloat16(v1);
                    __nv_bfloat16 l1 = __float2bfloat16(v1 - __bfloat162float(h1));
                    if (out_mode == 2) {   // V transposed [B,H,Dh,S]
                        size_t o0 = ((size_t)(b * NUM_HEADS + h) * HEAD_DIM + d) * SEQ + sq;
                        g_Vh[o0] = h0; g_Vl[o0] = l0;
                        g_Vh[o0 + SEQ] = h1; g_Vl[o0 + SEQ] = l1;
                    } else {
                        size_t o = (((size_t)b * NUM_HEADS + h) * SEQ + sq) * HEAD_DIM + d;
                        if (out_mode == 0) { st_bf2(&g_Qh[o], h0, h1); st_bf2(&g_Ql[o], l0, l1); }
                        else               { st_bf2(&g_Kh[o], h0, h1); st_bf2(&g_Kl[o], l0, l1); }
                    }
                }
            }
        }
}

__global__ __launch_bounds__(256) void gemm_qkv_kernel() {
    const __nv_bfloat16* A = blockIdx.z == 0 ? g_A2y : g_A2x;
    const __nv_bfloat16* Bw = blockIdx.z == 0 ? g_W2q : blockIdx.z == 1 ? g_W2k : g_W2v;
    gemm_core(A, Bw, nullptr, (int)blockIdx.z);
}

__global__ __launch_bounds__(256) void gemm_proj_kernel(float* __restrict__ out) {
    gemm_core(g_C2, g_W2o, out, 3);
}

// ---------------------------------------------------------------------------
// HMMA attention, 512 threads / 16 warps. Per CTA: (b,h), 128 q-rows;
// stream kv in 128-chunks. S warp tile 32x32, PV warp tile 32x16.
// ---------------------------------------------------------------------------
#define oQh 0
#define oQl 16384
#define oKh 32768
#define oKl 49152
#define oVh 65536
#define oVl 81920
#define oPh 98304
#define oPl 131072
#define oRS 163840
#define ASMEM_BYTES (163840 + 2048)

__global__ __launch_bounds__(512, 1)
void attn_hmma_kernel(const float* __restrict__ mask)
{
    extern __shared__ char smem[];
    const uint32_t sb = smem_u32(smem);
    const int tid = threadIdx.x, lane = tid & 31, warp = tid >> 5;
    const int wm  = (warp & 3) * 32;       // q offset of warp tile
    const int wn  = (warp >> 2) * 32;      // kv offset (S phase)
    const int wn2 = (warp >> 2) * 16;      // d offset (PV phase)
    const int lrow = lane & 15;
    const int lk16 = (lane >> 4) * 16;

    const int bh = blockIdx.y;
    const int b = bh >> 4, h = bh & 15;
    const int q0 = blockIdx.x * 128;

    const char* Qhp = (const char*)g_Qh + (size_t)bh * SEQ * HEAD_DIM * 2;
    const char* Qlp = (const char*)g_Ql + (size_t)bh * SEQ * HEAD_DIM * 2;
    const char* Khp = (const char*)g_Kh + (size_t)bh * SEQ * HEAD_DIM * 2;
    const char* Klp = (const char*)g_Kl + (size_t)bh * SEQ * HEAD_DIM * 2;
    const char* Vhp = (const char*)g_Vh + (size_t)bh * HEAD_DIM * SEQ * 2;
    const char* Vlp = (const char*)g_Vl + (size_t)bh * HEAD_DIM * SEQ * 2;

    // ---- load Q (hi+lo) and K chunk 0 ----
    #pragma unroll
    for (int t = 0; t < 2; t++) {
        int id = tid + t * 512;
        int r = id >> 3, cb = (id & 7) * 16;
        uint32_t so = SWZ(r * 128 + cb);
        CP_ASYNC16(sb + oQh + so, Qhp + (size_t)(q0 + r) * 128 + cb);
        CP_ASYNC16(sb + oQl + so, Qlp + (size_t)(q0 + r) * 128 + cb);
        CP_ASYNC16(sb + oKh + so, Khp + (size_t)r * 128 + cb);
        CP_ASYNC16(sb + oKl + so, Klp + (size_t)r * 128 + cb);
    }
    CP_COMMIT();

    float rs[4] = {0.f, 0.f, 0.f, 0.f};
    float oacc[2][2][4];
    #pragma unroll
    for (int i = 0; i < 2; i++)
        #pragma unroll
        for (int j = 0; j < 2; j++)
            #pragma unroll
            for (int q = 0; q < 4; q++) oacc[i][j][q] = 0.f;

    for (int c = 0; c < SEQ / 128; c++) {
        const int kv0 = c * 128;
        // prefetch V chunk (V^T rows d=0..63, 256B rows)
        #pragma unroll
        for (int t = 0; t < 2; t++) {
            int id = tid + t * 512;
            int r = id >> 4, cb = (id & 15) * 16;
            uint32_t so = SWZ256(r * 256 + cb);
            CP_ASYNC16(sb + oVh + so, Vhp + (size_t)r * (SEQ * 2) + kv0 * 2 + cb);
            CP_ASYNC16(sb + oVl + so, Vlp + (size_t)r * (SEQ * 2) + kv0 * 2 + cb);
        }
        CP_COMMIT();
        CP_WAIT1();           // K chunk (and Q on c==0) ready
        __syncthreads();

        // ---- S = Q K^T (3-term split), warp tile 32x32 ----
        float sacc[2][4][4];
        #pragma unroll
        for (int i = 0; i < 2; i++)
            #pragma unroll
            for (int j = 0; j < 4; j++)
                #pragma unroll
                for (int q = 0; q < 4; q++) sacc[i][j][q] = 0.f;

        #pragma unroll
        for (int kk = 0; kk < 4; kk++) {
            const int kb = kk * 32;
            uint32_t qh[2][4], ql[2][4];
            #pragma unroll
            for (int mi = 0; mi < 2; mi++) {
                uint32_t ro = SWZ((wm + mi * 16 + lrow) * 128 + kb + lk16);
                ldsm_x4(qh[mi], sb + oQh + ro);
                ldsm_x4(ql[mi], sb + oQl + ro);
            }
            #pragma unroll
            for (int njg = 0; njg < 2; njg++) {
                uint32_t kh[4], kl[4];
                uint32_t ro = SWZ((wn + njg * 16 + lrow) * 128 + kb + lk16);
                ldsm_x4(kh, sb + oKh + ro);
                ldsm_x4(kl, sb + oKl + ro);
                #pragma unroll
                for (int mi = 0; mi < 2; mi++) {
                    mma_bf16(sacc[mi][njg * 2],     qh[mi], kh[0], kh[2]);
                    mma_bf16(sacc[mi][njg * 2 + 1], qh[mi], kh[1], kh[3]);
                    mma_bf16(sacc[mi][njg * 2],     qh[mi], kl[0], kl[2]);
                    mma_bf16(sacc[mi][njg * 2 + 1], qh[mi], kl[1], kl[3]);
                    mma_bf16(sacc[mi][njg * 2],     ql[mi], kh[0], kh[2]);
                    mma_bf16(sacc[mi][njg * 2 + 1], ql[mi], kh[1], kh[3]);
                }
            }
        }

        // ---- softmax: mask + exp, rowsum, split P to smem ----
        #pragma unroll
        for (int mi = 0; mi < 2; mi++)
            #pragma unroll
            for (int nj = 0; nj < 4; nj++)
                #pragma unroll
                for (int half = 0; half < 2; half++) {
                    int rl = wm + mi * 16 + (lane >> 2) + half * 8;
                    int cl = wn + nj * 8 + (lane & 3) * 2;
                    float2 mk = *(const float2*)&mask[(size_t)(q0 + rl) * SEQ + kv0 + cl];
                    float e0 = __expf(sacc[mi][nj][half * 2]     + mk.x);
                    float e1 = __expf(sacc[mi][nj][half * 2 + 1] + mk.y);
                    rs[mi * 2 + half] += e0 + e1;
                    __nv_bfloat16 h0 = __float2bfloat16(e0);
                    __nv_bfloat16 l0 = __float2bfloat16(e0 - __bfloat162float(h0));
                    __nv_bfloat16 h1 = __float2bfloat16(e1);
                    __nv_bfloat16 l1 = __float2bfloat16(e1 - __bfloat162float(h1));
                    uint32_t po = SWZ256(rl * 256 + cl * 2);
                    st_bf2((__nv_bfloat16*)(smem + oPh + po), h0, h1);
                    st_bf2((__nv_bfloat16*)(smem + oPl + po), l0, l1);
                }

        CP_WAIT0();           // V chunk ready
        __syncthreads();      // P fully written, K reads done

        // prefetch next K chunk (overlaps PV)
        if (c + 1 < SEQ / 128) {
            const int kvn = (c + 1) * 128;
            #pragma unroll
            for (int t = 0; t < 2; t++) {
                int id = tid + t * 512;
                int r = id >> 3, cb = (id & 7) * 16;
                uint32_t so = SWZ(r * 128 + cb);
                CP_ASYNC16(sb + oKh + so, Khp + (size_t)(kvn + r) * 128 + cb);
                CP_ASYNC16(sb + oKl + so, Klp + (size_t)(kvn + r) * 128 + cb);
            }
            CP_COMMIT();
        }

        // ---- O += P V (3-term split), k=128, warp tile 32x16 ----
        #pragma unroll
        for (int kk = 0; kk < 8; kk++) {
            const int kb = kk * 32;
            uint32_t ph[2][4], pl[2][4];
            #pragma unroll
            for (int mi = 0; mi < 2; mi++) {
                uint32_t ro = SWZ256((wm + mi * 16 + lrow) * 256 + kb + lk16);
                ldsm_x4(ph[mi], sb + oPh + ro);
                ldsm_x4(pl[mi], sb + oPl + ro);
            }
            uint32_t vh[4], vl[4];
            uint32_t ro = SWZ256((wn2 + lrow) * 256 + kb + lk16);
            ldsm_x4(vh, sb + oVh + ro);
            ldsm_x4(vl, sb + oVl + ro);
            #pragma unroll
            for (int mi = 0; mi < 2; mi++) {
                mma_bf16(oacc[mi][0], ph[mi], vh[0], vh[2]);
                mma_bf16(oacc[mi][1], ph[mi], vh[1], vh[3]);
                mma_bf16(oacc[mi][0], ph[mi], vl[0], vl[2]);
                mma_bf16(oacc[mi][1], ph[mi], vl[1], vl[3]);
                mma_bf16(oacc[mi][0], pl[mi], vh[0], vh[2]);
                mma_bf16(oacc[mi][1], pl[mi], vh[1], vh[3]);
            }
        }
        __syncthreads();      // V/P buffers reusable next chunk
    }

    // ---- rowsum: quad butterfly + cross-warp-group reduce ----
    #pragma unroll
    for (int i = 0; i < 4; i++) {
        rs[i] += __shfl_xor_sync(0xffffffffu, rs[i], 1);
        rs[i] += __shfl_xor_sync(0xffffffffu, rs[i], 2);
    }
    float* rsm = (float*)(smem + oRS);   // [4][128]
    if ((lane & 3) == 0) {
        #pragma unroll
        for (int mi = 0; mi < 2; mi++)
            #pragma unroll
            for (int half = 0; half < 2; half++)
                rsm[(warp >> 2) * 128 + wm + mi * 16 + (lane >> 2) + half * 8] = rs[mi * 2 + half];
    }
    __syncthreads();

    // ---- normalize + write split ctx into g_C2 [4096][3072] ([hi|hi|lo]) ----
    #pragma unroll
    for (int mi = 0; mi < 2; mi++)
        #pragma unroll
        for (int nj = 0; nj < 2; nj++)
            #pragma unroll
            for (int half = 0; half < 2; half++) {
                int rl = wm + mi * 16 + (lane >> 2) + half * 8;
                float inv = 1.f / (rsm[rl] + rsm[128 + rl] + rsm[256 + rl] + rsm[384 + rl] + 1e-10f);
                int sq = q0 + rl;
                int dc = wn2 + nj * 8 + (lane & 3) * 2;
                float v0 = oacc[mi][nj][half * 2] * inv;
                float v1 = oacc[mi][nj][half * 2 + 1] * inv;
                __nv_bfloat16 h0 = __float2bfloat16(v0);
                __nv_bfloat16 l0 = __float2bfloat16(v0 - __bfloat162float(h0));
                __nv_bfloat16 h1 = __float2bfloat16(v1);
                __nv_bfloat16 l1 = __float2bfloat16(v1 - __bfloat162float(h1));
                size_t o = (size_t)(b * SEQ + sq) * KEFF + h * HEAD_DIM + dc;
                st_bf2(&g_C2[o], h0, h1);
                st_bf2(&g_C2[o + 1024], h0, h1);
                st_bf2(&g_C2[o + 2048], l0, l1);
            }
}

// ---------------------------------------------------------------------------
// Launch
// ---------------------------------------------------------------------------
extern "C" void kernel_launch(void* const* d_in, const int* in_sizes, int n_in,
                              void* d_out, int out_size)
{
    (void)in_sizes; (void)n_in; (void)out_size;
    const float* x    = (const float*)d_in[0];
    const float* y    = (const float*)d_in[1];
    const float* mask = (const float*)d_in[2];
    const float* Wq   = (const float*)d_in[3];
    const float* Wk   = (const float*)d_in[4];
    const float* Wv   = (const float*)d_in[5];
    const float* Wo   = (const float*)d_in[6];
    float* out = (float*)d_out;

    cudaFuncSetAttribute(gemm_qkv_kernel, cudaFuncAttributeMaxDynamicSharedMemorySize, GSMEM_BYTES);
    cudaFuncSetAttribute(gemm_proj_kernel, cudaFuncAttributeMaxDynamicSharedMemorySize, GSMEM_BYTES);
    cudaFuncSetAttribute(attn_hmma_kernel, cudaFuncAttributeMaxDynamicSharedMemorySize, ASMEM_BYTES);

    // 1) split conversions
    {
        dim3 g((NROWS * 1024) / 256, 1, 2);
        split_inputs_kernel<<<g, 256>>>(x, y);
        dim3 gw((1024 * 1024) / 256, 1, 4);
        split_w_kernel<<<gw, 256>>>(Wq, Wk, Wv, Wo);
    }
    // 2) QKV projections (HMMA) -> split Q/K/V
    {
        dim3 g(D_MODEL / 128, NROWS / 128, 3);
        gemm_qkv_kernel<<<g, 256, GSMEM_BYTES>>>();
    }
    // 3) Attention (HMMA, split-bf16, 512 threads) -> split ctx
    {
        dim3 g(SEQ / 128, BATCH * NUM_HEADS);
        attn_hmma_kernel<<<g, 512, ASMEM_BYTES>>>(mask);
    }
    // 4) Output projection (HMMA)
    {
        dim3 g(D_MODEL / 128, NROWS / 128);
        gemm_proj_kernel<<<g, 256, GSMEM_BYTES>>>(out);
    }
}

// round 14
// speedup vs baseline: 2.3411x; 1.0196x over previous
#include <cuda_runtime.h>
#include <cuda_bf16.h>
#include <cstdint>

#define D_MODEL 1024
#define NUM_HEADS 16
#define HEAD_DIM 64
#define SEQ 2048
#define BATCH 2
#define NROWS (BATCH * SEQ)   // 4096
#define KEFF 3072             // split-bf16: [hi|hi|lo] x [hi|lo|hi]
#define KSLAB 64
#define NSLAB (KEFF / KSLAB)  // 48

// ---------------------------------------------------------------------------
// Scratch (__device__ globals; allocation-free rule)
// ---------------------------------------------------------------------------
__device__ __nv_bfloat16 g_A2x[(size_t)NROWS * KEFF];
__device__ __nv_bfloat16 g_A2y[(size_t)NROWS * KEFF];
__device__ __nv_bfloat16 g_C2[(size_t)NROWS * KEFF];          // split ctx (attn writes)
__device__ __nv_bfloat16 g_W2q[(size_t)D_MODEL * KEFF];
__device__ __nv_bfloat16 g_W2k[(size_t)D_MODEL * KEFF];
__device__ __nv_bfloat16 g_W2v[(size_t)D_MODEL * KEFF];
__device__ __nv_bfloat16 g_W2o[(size_t)D_MODEL * KEFF];
// split Q/K: [B,H,S,Dh]; split V transposed: [B,H,Dh,S]
__device__ __nv_bfloat16 g_Qh[(size_t)NROWS * D_MODEL];
__device__ __nv_bfloat16 g_Ql[(size_t)NROWS * D_MODEL];
__device__ __nv_bfloat16 g_Kh[(size_t)NROWS * D_MODEL];
__device__ __nv_bfloat16 g_Kl[(size_t)NROWS * D_MODEL];
__device__ __nv_bfloat16 g_Vh[(size_t)NROWS * D_MODEL];
__device__ __nv_bfloat16 g_Vl[(size_t)NROWS * D_MODEL];

// ---------------------------------------------------------------------------
// Helpers (baseline PTX only)
// ---------------------------------------------------------------------------
__device__ __forceinline__ uint32_t smem_u32(const void* p) {
    uint32_t a;
    asm("{ .reg .u64 t; cvta.to.shared.u64 t, %1; cvt.u32.u64 %0, t; }" : "=r"(a) : "l"(p));
    return a;
}
#define SWZ(o)    ((o) ^ (((o) >> 3) & 0x70))   // 128B rows
#define SWZ256(o) ((o) ^ (((o) >> 4) & 0x70))   // 256B rows

__device__ __forceinline__ void ldsm_x4(uint32_t* r, uint32_t addr) {
    asm volatile("ldmatrix.sync.aligned.m8n8.x4.shared.b16 {%0,%1,%2,%3}, [%4];"
        : "=r"(r[0]), "=r"(r[1]), "=r"(r[2]), "=r"(r[3]) : "r"(addr));
}
__device__ __forceinline__ void mma_bf16(float* c, const uint32_t* a, uint32_t b0, uint32_t b1) {
    asm volatile(
        "mma.sync.aligned.m16n8k16.row.col.f32.bf16.bf16.f32 "
        "{%0,%1,%2,%3}, {%4,%5,%6,%7}, {%8,%9}, {%0,%1,%2,%3};"
        : "+f"(c[0]), "+f"(c[1]), "+f"(c[2]), "+f"(c[3])
        : "r"(a[0]), "r"(a[1]), "r"(a[2]), "r"(a[3]), "r"(b0), "r"(b1));
}
#define CP_ASYNC16(dst, src) \
    asm volatile("cp.async.cg.shared.global [%0], [%1], 16;" :: "r"(dst), "l"(src))
#define CP_COMMIT() asm volatile("cp.async.commit_group;" ::: "memory")
#define CP_WAIT1()  asm volatile("cp.async.wait_group 1;" ::: "memory")
#define CP_WAIT0()  asm volatile("cp.async.wait_group 0;" ::: "memory")

__device__ __forceinline__ void st_bf2(__nv_bfloat16* p, __nv_bfloat16 a, __nv_bfloat16 b) {
    __nv_bfloat162 t; t.x = a; t.y = b;
    *(__nv_bfloat162*)p = t;
}
__device__ __forceinline__ uint32_t pack_bf2(float a, float b) {
    __nv_bfloat162 t; t.x = __float2bfloat16(a); t.y = __float2bfloat16(b);
    return *(uint32_t*)&t;
}

// ---------------------------------------------------------------------------
// Split-bf16 conversion kernels (inputs + weights)
// ---------------------------------------------------------------------------
__device__ __forceinline__ void split_write(__nv_bfloat16* out, size_t o, float v, int patB) {
    __nv_bfloat16 hi = __float2bfloat16(v);
    __nv_bfloat16 lo = __float2bfloat16(v - __bfloat162float(hi));
    if (patB) { out[o] = hi; out[o + 1024] = lo; out[o + 2048] = hi; }
    else      { out[o] = hi; out[o + 1024] = hi; out[o + 2048] = lo; }
}

__global__ void split_inputs_kernel(const float* __restrict__ x, const float* __restrict__ y) {
    int idx = blockIdx.x * blockDim.x + threadIdx.x;
    const float* in = blockIdx.z ? x : y;
    __nv_bfloat16* out = blockIdx.z ? g_A2x : g_A2y;
    int r = idx >> 10, c = idx & 1023;
    split_write(out, (size_t)r * KEFF + c, in[idx], 0);
}

__global__ void split_w_kernel(const float* __restrict__ Wq, const float* __restrict__ Wk,
                               const float* __restrict__ Wv, const float* __restrict__ Wo) {
    int idx = blockIdx.x * blockDim.x + threadIdx.x;
    const float* in = blockIdx.z == 0 ? Wq : blockIdx.z == 1 ? Wk : blockIdx.z == 2 ? Wv : Wo;
    __nv_bfloat16* out = blockIdx.z == 0 ? g_W2q : blockIdx.z == 1 ? g_W2k
                       : blockIdx.z == 2 ? g_W2v : g_W2o;
    float scale = (blockIdx.z == 0) ? 0.125f : 1.0f;    // fold 1/sqrt(Dh) into Wq
    int r = idx >> 10, c = idx & 1023;
    split_write(out, (size_t)r * KEFF + c, in[idx] * scale, 1);
}

// ---------------------------------------------------------------------------
// HMMA GEMM (unchanged from R10): 3-stage cp.async pipeline.
// ---------------------------------------------------------------------------
#define GSMEM_BYTES (6 * 16384)

__device__ __forceinline__ void load_slab(const __nv_bfloat16* A, const __nv_bfloat16* Bw,
                                          uint32_t sb, int m0, int n0, int s, int buf) {
    const int tid = threadIdx.x;
    const int k0 = s * KSLAB;
    const uint32_t abase = sb + buf * 32768;
    const uint32_t bbase = abase + 16384;
    #pragma unroll
    for (int t = 0; t < 4; t++) {
        int id = tid + t * 256;
        int r = id >> 3, cb = (id & 7) * 16;
        const char* ga = (const char*)A + ((size_t)(m0 + r) * KEFF + k0) * 2 + cb;
        const char* gb = (const char*)Bw + ((size_t)(n0 + r) * KEFF + k0) * 2 + cb;
        CP_ASYNC16(abase + SWZ(r * 128 + cb), ga);
        CP_ASYNC16(bbase + SWZ(r * 128 + cb), gb);
    }
    CP_COMMIT();
}

__device__ __forceinline__ void gemm_core(const __nv_bfloat16* __restrict__ A,
                                          const __nv_bfloat16* __restrict__ Bw,
                                          float* __restrict__ out, int out_mode) {
    extern __shared__ char smem[];
    const uint32_t sb = smem_u32(smem);
    const int tid = threadIdx.x, lane = tid & 31, warp = tid >> 5;
    const int wm = (warp & 3) * 32;
    const int wn = (warp >> 2) * 64;
    const int m0 = blockIdx.y * 128, n0 = blockIdx.x * 128;

    float acc[2][8][4];
    #pragma unroll
    for (int i = 0; i < 2; i++)
        #pragma unroll
        for (int j = 0; j < 8; j++)
            #pragma unroll
            for (int q = 0; q < 4; q++) acc[i][j][q] = 0.f;

    load_slab(A, Bw, sb, m0, n0, 0, 0);
    load_slab(A, Bw, sb, m0, n0, 1, 1);

    const int lrow = lane & 15;
    const int lk16 = (lane >> 4) * 16;

    int buf = 0;
    for (int s = 0; s < NSLAB; s++) {
        if (s + 1 < NSLAB) CP_WAIT1(); else CP_WAIT0();
        __syncthreads();
        if (s + 2 < NSLAB) {
            int nbuf = buf + 2; if (nbuf >= 3) nbuf -= 3;
            load_slab(A, Bw, sb, m0, n0, s + 2, nbuf);
        }
        const uint32_t abase = sb + buf * 32768;
        const uint32_t bbase = abase + 16384;

        #pragma unroll
        for (int kk = 0; kk < 4; kk++) {
            const int kb = kk * 32;
            uint32_t a_r[2][4], b_r[4][4];
            #pragma unroll
            for (int mi = 0; mi < 2; mi++)
                ldsm_x4(a_r[mi], abase + SWZ((wm + mi * 16 + lrow) * 128 + kb + lk16));
            #pragma unroll
            for (int nj = 0; nj < 4; nj++)
                ldsm_x4(b_r[nj], bbase + SWZ((wn + nj * 16 + lrow) * 128 + kb + lk16));
            #pragma unroll
            for (int mi = 0; mi < 2; mi++)
                #pragma unroll
                for (int nj = 0; nj < 4; nj++) {
                    mma_bf16(acc[mi][nj * 2],     a_r[mi], b_r[nj][0], b_r[nj][2]);
                    mma_bf16(acc[mi][nj * 2 + 1], a_r[mi], b_r[nj][1], b_r[nj][3]);
                }
        }
        buf++; if (buf >= 3) buf = 0;
    }

    #pragma unroll
    for (int mi = 0; mi < 2; mi++)
        #pragma unroll
        for (int nj = 0; nj < 8; nj++) {
            #pragma unroll
            for (int half = 0; half < 2; half++) {
                int m = m0 + wm + mi * 16 + (lane >> 2) + half * 8;
                int n = n0 + wn + nj * 8 + (lane & 3) * 2;
                float v0 = acc[mi][nj][half * 2], v1 = acc[mi][nj][half * 2 + 1];
                if (out_mode == 3) {
                    out[(size_t)m * D_MODEL + n] = v0;
                    out[(size_t)m * D_MODEL + n + 1] = v1;
                } else {
                    int b = m >> 11, sq = m & (SEQ - 1);
                    int h = n >> 6, d = n & (HEAD_DIM - 1);
                    __nv_bfloat16 h0 = __float2bfloat16(v0);
                    __nv_bfloat16 l0 = __float2bfloat16(v0 - __bfloat162float(h0));
                    __nv_bfloat16 h1 = __float2bfloat16(v1);
                    __nv_bfloat16 l1 = __float2bfloat16(v1 - __bfloat162float(h1));
                    if (out_mode == 2) {   // V transposed [B,H,Dh,S]
                        size_t o0 = ((size_t)(b * NUM_HEADS + h) * HEAD_DIM + d) * SEQ + sq;
                        g_Vh[o0] = h0; g_Vl[o0] = l0;
                        g_Vh[o0 + SEQ] = h1; g_Vl[o0 + SEQ] = l1;
                    } else {
                        size_t o = (((size_t)b * NUM_HEADS + h) * SEQ + sq) * HEAD_DIM + d;
                        if (out_mode == 0) { st_bf2(&g_Qh[o], h0, h1); st_bf2(&g_Ql[o], l0, l1); }
                        else               { st_bf2(&g_Kh[o], h0, h1); st_bf2(&g_Kl[o], l0, l1); }
                    }
                }
            }
        }
}

__global__ __launch_bounds__(256) void gemm_qkv_kernel() {
    const __nv_bfloat16* A = blockIdx.z == 0 ? g_A2y : g_A2x;
    const __nv_bfloat16* Bw = blockIdx.z == 0 ? g_W2q : blockIdx.z == 1 ? g_W2k : g_W2v;
    gemm_core(A, Bw, nullptr, (int)blockIdx.z);
}

__global__ __launch_bounds__(256) void gemm_proj_kernel(float* __restrict__ out) {
    gemm_core(g_C2, g_W2o, out, 3);
}

// ---------------------------------------------------------------------------
// HMMA attention v2: P kept in registers (C-frag == A-frag repack).
// 512 threads / 16 warps = 8 q-groups (m16) x 2 kv-groups (64 kv each).
// Each warp: S(16q x 64kv) -> exp -> pack A-frags -> partial PV(16q x 64d).
// Cross-warp (kv-group) reduction once at the end.
// smem: Qh/Ql 32K | Kh/Kl 32K | Vh/Vl 32K | rsm 1K. Scratch reuses Q at end.
// ---------------------------------------------------------------------------
#define oQh 0
#define oQl 16384
#define oKh 32768
#define oKl 49152
#define oVh 65536
#define oVl 81920
#define oRS 98304
#define ASMEM_BYTES (98304 + 1024)

__global__ __launch_bounds__(512, 1)
void attn_hmma_kernel(const float* __restrict__ mask)
{
    extern __shared__ char smem[];
    const uint32_t sb = smem_u32(smem);
    const int tid = threadIdx.x, lane = tid & 31, warp = tid >> 5;
    const int wm = (warp & 7) * 16;        // q offset (16 rows per warp)
    const int g  = warp >> 3;              // kv-group 0/1
    const int wn = g * 64;                 // kv offset within chunk
    const int lrow = lane & 15;
    const int lk16 = (lane >> 4) * 16;

    const int bh = blockIdx.y;
    const int b = bh >> 4, h = bh & 15;
    const int q0 = blockIdx.x * 128;

    const char* Qhp = (const char*)g_Qh + (size_t)bh * SEQ * HEAD_DIM * 2;
    const char* Qlp = (const char*)g_Ql + (size_t)bh * SEQ * HEAD_DIM * 2;
    const char* Khp = (const char*)g_Kh + (size_t)bh * SEQ * HEAD_DIM * 2;
    const char* Klp = (const char*)g_Kl + (size_t)bh * SEQ * HEAD_DIM * 2;
    const char* Vhp = (const char*)g_Vh + (size_t)bh * HEAD_DIM * SEQ * 2;
    const char* Vlp = (const char*)g_Vl + (size_t)bh * HEAD_DIM * SEQ * 2;

    // ---- preload: group A = Q + K0, group B = V0 ----
    #pragma unroll
    for (int t = 0; t < 2; t++) {
        int id = tid + t * 512;
        int r = id >> 3, cb = (id & 7) * 16;
        uint32_t so = SWZ(r * 128 + cb);
        CP_ASYNC16(sb + oQh + so, Qhp + (size_t)(q0 + r) * 128 + cb);
        CP_ASYNC16(sb + oQl + so, Qlp + (size_t)(q0 + r) * 128 + cb);
        CP_ASYNC16(sb + oKh + so, Khp + (size_t)r * 128 + cb);
        CP_ASYNC16(sb + oKl + so, Klp + (size_t)r * 128 + cb);
    }
    CP_COMMIT();
    #pragma unroll
    for (int t = 0; t < 2; t++) {
        int id = tid + t * 512;
        int r = id >> 4, cb = (id & 15) * 16;
        uint32_t so = SWZ256(r * 256 + cb);
        CP_ASYNC16(sb + oVh + so, Vhp + (size_t)r * (SEQ * 2) + cb);
        CP_ASYNC16(sb + oVl + so, Vlp + (size_t)r * (SEQ * 2) + cb);
    }
    CP_COMMIT();

    float rs[2] = {0.f, 0.f};
    float oacc[8][4];
    #pragma unroll
    for (int j = 0; j < 8; j++)
        #pragma unroll
        for (int q = 0; q < 4; q++) oacc[j][q] = 0.f;

    const int mrow = q0 + wm + (lane >> 2);
    const int mcol0 = wn + (lane & 3) * 2;

    for (int c = 0; c < SEQ / 128; c++) {
        const int kv0 = c * 128;
        // K[c] ready (all but most-recent group = V[c])
        CP_WAIT1();
        __syncthreads();

        // ---- S = Q K^T (3-term split), warp tile 16q x 64kv ----
        float sacc[8][4];
        #pragma unroll
        for (int j = 0; j < 8; j++)
            #pragma unroll
            for (int q = 0; q < 4; q++) sacc[j][q] = 0.f;

        #pragma unroll
        for (int kk = 0; kk < 4; kk++) {
            const int kb = kk * 32;
            uint32_t qh[4], ql[4];
            uint32_t qro = SWZ((wm + lrow) * 128 + kb + lk16);
            ldsm_x4(qh, sb + oQh + qro);
            ldsm_x4(ql, sb + oQl + qro);
            #pragma unroll
            for (int njg = 0; njg < 4; njg++) {
                uint32_t kh[4], kl[4];
                uint32_t ro = SWZ((wn + njg * 16 + lrow) * 128 + kb + lk16);
                ldsm_x4(kh, sb + oKh + ro);
                ldsm_x4(kl, sb + oKl + ro);
                mma_bf16(sacc[njg * 2],     qh, kh[0], kh[2]);
                mma_bf16(sacc[njg * 2 + 1], qh, kh[1], kh[3]);
                mma_bf16(sacc[njg * 2],     qh, kl[0], kl[2]);
                mma_bf16(sacc[njg * 2 + 1], qh, kl[1], kl[3]);
                mma_bf16(sacc[njg * 2],     ql, kh[0], kh[2]);
                mma_bf16(sacc[njg * 2 + 1], ql, kh[1], kh[3]);
            }
        }

        // ---- softmax: mask + exp (in regs), rowsum ----
        #pragma unroll
        for (int nj = 0; nj < 8; nj++)
            #pragma unroll
            for (int half = 0; half < 2; half++) {
                float2 mk = *(const float2*)&mask[(size_t)(mrow + half * 8) * SEQ + kv0 + mcol0 + nj * 8];
                float e0 = __expf(sacc[nj][half * 2]     + mk.x);
                float e1 = __expf(sacc[nj][half * 2 + 1] + mk.y);
                rs[half] += e0 + e1;
                sacc[nj][half * 2]     = e0;
                sacc[nj][half * 2 + 1] = e1;
            }

        // V[c] ready; K buffer free
        CP_WAIT0();
        __syncthreads();
        if (c + 1 < SEQ / 128) {       // prefetch K[c+1] (overlaps PV)
            const int kvn = (c + 1) * 128;
            #pragma unroll
            for (int t = 0; t < 2; t++) {
                int id = tid + t * 512;
                int r = id >> 3, cb = (id & 7) * 16;
                uint32_t so = SWZ(r * 128 + cb);
                CP_ASYNC16(sb + oKh + so, Khp + (size_t)(kvn + r) * 128 + cb);
                CP_ASYNC16(sb + oKl + so, Klp + (size_t)(kvn + r) * 128 + cb);
            }
            CP_COMMIT();
        }

        // ---- partial PV: P from registers (C-frag -> A-frag repack) ----
        #pragma unroll
        for (int kk2 = 0; kk2 < 4; kk2++) {
            // A-frags for k16 block kk2 from S tiles nj = 2*kk2, 2*kk2+1
            uint32_t aph[4], apl[4];
            {
                const float* s0 = sacc[kk2 * 2];
                const float* s1 = sacc[kk2 * 2 + 1];
                aph[0] = pack_bf2(s0[0], s0[1]);
                aph[1] = pack_bf2(s0[2], s0[3]);
                aph[2] = pack_bf2(s1[0], s1[1]);
                aph[3] = pack_bf2(s1[2], s1[3]);
                const __nv_bfloat162* hp0 = (const __nv_bfloat162*)&aph[0];
                const __nv_bfloat162* hp1 = (const __nv_bfloat162*)&aph[1];
                const __nv_bfloat162* hp2 = (const __nv_bfloat162*)&aph[2];
                const __nv_bfloat162* hp3 = (const __nv_bfloat162*)&aph[3];
                apl[0] = pack_bf2(s0[0] - __bfloat162float(hp0->x), s0[1] - __bfloat162float(hp0->y));
                apl[1] = pack_bf2(s0[2] - __bfloat162float(hp1->x), s0[3] - __bfloat162float(hp1->y));
                apl[2] = pack_bf2(s1[0] - __bfloat162float(hp2->x), s1[1] - __bfloat162float(hp2->y));
                apl[3] = pack_bf2(s1[2] - __bfloat162float(hp3->x), s1[3] - __bfloat162float(hp3->y));
            }
            const int kbyte = wn * 2 + kk2 * 32;   // kv byte offset in V^T row
            #pragma unroll
            for (int dg = 0; dg < 4; dg++) {
                uint32_t vh[4], vl[4];
                uint32_t ro = SWZ256((dg * 16 + lrow) * 256 + kbyte + lk16);
                ldsm_x4(vh, sb + oVh + ro);
                ldsm_x4(vl, sb + oVl + ro);
                mma_bf16(oacc[dg * 2],     aph, vh[0], vh[2]);
                mma_bf16(oacc[dg * 2 + 1], aph, vh[1], vh[3]);
                mma_bf16(oacc[dg * 2],     aph, vl[0], vl[2]);
                mma_bf16(oacc[dg * 2 + 1], aph, vl[1], vl[3]);
                mma_bf16(oacc[dg * 2],     apl, vh[0], vh[2]);
                mma_bf16(oacc[dg * 2 + 1], apl, vh[1], vh[3]);
            }
        }
        __syncthreads();               // V buffer free
        if (c + 1 < SEQ / 128) {       // prefetch V[c+1] (overlaps next S)
            const int kvn = (c + 1) * 128;
            #pragma unroll
            for (int t = 0; t < 2; t++) {
                int id = tid + t * 512;
                int r = id >> 4, cb = (id & 15) * 16;
                uint32_t so = SWZ256(r * 256 + cb);
                CP_ASYNC16(sb + oVh + so, Vhp + (size_t)r * (SEQ * 2) + kvn * 2 + cb);
                CP_ASYNC16(sb + oVl + so, Vlp + (size_t)r * (SEQ * 2) + kvn * 2 + cb);
            }
            CP_COMMIT();
        }
    }

    // ---- rowsum: quad butterfly, per-group partials ----
    #pragma unroll
    for (int i = 0; i < 2; i++) {
        rs[i] += __shfl_xor_sync(0xffffffffu, rs[i], 1);
        rs[i] += __shfl_xor_sync(0xffffffffu, rs[i], 2);
    }
    float* rsm = (float*)(smem + oRS);   // [2][128]
    if ((lane & 3) == 0) {
        #pragma unroll
        for (int half = 0; half < 2; half++)
            rsm[g * 128 + wm + (lane >> 2) + half * 8] = rs[half];
    }

    // ---- cross-kv-group reduction of partial O (scratch over dead Q smem) ----
    const int wmw = warp & 7;
    float* scr = (float*)(smem + wmw * 4096);   // 16 rows x 64 cols fp32 per warp
    if (g == 1) {
        #pragma unroll
        for (int nj = 0; nj < 8; nj++)
            #pragma unroll
            for (int half = 0; half < 2; half++) {
                int rl = (lane >> 2) + half * 8;
                int dc = nj * 8 + (lane & 3) * 2;
                *(float2*)&scr[rl * 64 + dc] = *(float2*)&oacc[nj][half * 2];
            }
    }
    __syncthreads();

    if (g == 0) {
        #pragma unroll
        for (int nj = 0; nj < 8; nj++)
            #pragma unroll
            for (int half = 0; half < 2; half++) {
                int rl = (lane >> 2) + half * 8;
                int dc = nj * 8 + (lane & 3) * 2;
                float2 part = *(float2*)&scr[rl * 64 + dc];
                int row = wm + rl;
                float inv = 1.f / (rsm[row] + rsm[128 + row] + 1e-10f);
                float v0 = (oacc[nj][half * 2]     + part.x) * inv;
                float v1 = (oacc[nj][half * 2 + 1] + part.y) * inv;
                __nv_bfloat16 h0 = __float2bfloat16(v0);
                __nv_bfloat16 l0 = __float2bfloat16(v0 - __bfloat162float(h0));
                __nv_bfloat16 h1 = __float2bfloat16(v1);
                __nv_bfloat16 l1 = __float2bfloat16(v1 - __bfloat162float(h1));
                size_t o = (size_t)(b * SEQ + q0 + row) * KEFF + h * HEAD_DIM + dc;
                st_bf2(&g_C2[o], h0, h1);
                st_bf2(&g_C2[o + 1024], h0, h1);
                st_bf2(&g_C2[o + 2048], l0, l1);
            }
    }
}

// ---------------------------------------------------------------------------
// Launch
// ---------------------------------------------------------------------------
extern "C" void kernel_launch(void* const* d_in, const int* in_sizes, int n_in,
                              void* d_out, int out_size)
{
    (void)in_sizes; (void)n_in; (void)out_size;
    const float* x    = (const float*)d_in[0];
    const float* y    = (const float*)d_in[1];
    const float* mask = (const float*)d_in[2];
    const float* Wq   = (const float*)d_in[3];
    const float* Wk   = (const float*)d_in[4];
    const float* Wv   = (const float*)d_in[5];
    const float* Wo   = (const float*)d_in[6];
    float* out = (float*)d_out;

    cudaFuncSetAttribute(gemm_qkv_kernel, cudaFuncAttributeMaxDynamicSharedMemorySize, GSMEM_BYTES);
    cudaFuncSetAttribute(gemm_proj_kernel, cudaFuncAttributeMaxDynamicSharedMemorySize, GSMEM_BYTES);
    cudaFuncSetAttribute(attn_hmma_kernel, cudaFuncAttributeMaxDynamicSharedMemorySize, ASMEM_BYTES);

    // 1) split conversions
    {
        dim3 g((NROWS * 1024) / 256, 1, 2);
        split_inputs_kernel<<<g, 256>>>(x, y);
        dim3 gw((1024 * 1024) / 256, 1, 4);
        split_w_kernel<<<gw, 256>>>(Wq, Wk, Wv, Wo);
    }
    // 2) QKV projections (HMMA) -> split Q/K/V
    {
        dim3 g(D_MODEL / 128, NROWS / 128, 3);
        gemm_qkv_kernel<<<g, 256, GSMEM_BYTES>>>();
    }
    // 3) Attention (HMMA, P-in-registers) -> split ctx
    {
        dim3 g(SEQ / 128, BATCH * NUM_HEADS);
        attn_hmma_kernel<<<g, 512, ASMEM_BYTES>>>(mask);
    }
    // 4) Output projection (HMMA)
    {
        dim3 g(D_MODEL / 128, NROWS / 128);
        gemm_proj_kernel<<<g, 256, GSMEM_BYTES>>>(out);
    }
}

// round 17
// speedup vs baseline: 3.0683x; 1.3106x over previous
#include <cuda_runtime.h>
#include <cuda_bf16.h>
#include <cuda_fp16.h>
#include <cstdint>

#define D_MODEL 1024
#define NUM_HEADS 16
#define HEAD_DIM 64
#define SEQ 2048
#define BATCH 2
#define NROWS (BATCH * SEQ)   // 4096
#define KEFF 3072             // split-bf16: [hi|hi|lo] x [hi|lo|hi]
#define KSLAB 64
#define NSLAB (KEFF / KSLAB)  // 48

// ---------------------------------------------------------------------------
// Scratch (__device__ globals; allocation-free rule)
// ---------------------------------------------------------------------------
__device__ __nv_bfloat16 g_A2x[(size_t)NROWS * KEFF];
__device__ __nv_bfloat16 g_A2y[(size_t)NROWS * KEFF];
__device__ __nv_bfloat16 g_C2[(size_t)NROWS * KEFF];          // split ctx (attn writes)
__device__ __nv_bfloat16 g_W2q[(size_t)D_MODEL * KEFF];
__device__ __nv_bfloat16 g_W2k[(size_t)D_MODEL * KEFF];
__device__ __nv_bfloat16 g_W2v[(size_t)D_MODEL * KEFF];
__device__ __nv_bfloat16 g_W2o[(size_t)D_MODEL * KEFF];
// fp16 single-precision attention operands: Q/K [B,H,S,Dh]; V transposed [B,H,Dh,S]
__device__ __half g_Qf[(size_t)NROWS * D_MODEL];
__device__ __half g_Kf[(size_t)NROWS * D_MODEL];
__device__ __half g_Vf[(size_t)NROWS * D_MODEL];

// ---------------------------------------------------------------------------
// Helpers (baseline PTX only)
// ---------------------------------------------------------------------------
__device__ __forceinline__ uint32_t smem_u32(const void* p) {
    uint32_t a;
    asm("{ .reg .u64 t; cvta.to.shared.u64 t, %1; cvt.u32.u64 %0, t; }" : "=r"(a) : "l"(p));
    return a;
}
#define SWZ(o)    ((o) ^ (((o) >> 3) & 0x70))   // 128B rows
#define SWZ256(o) ((o) ^ (((o) >> 4) & 0x70))   // 256B rows

__device__ __forceinline__ void ldsm_x4(uint32_t* r, uint32_t addr) {
    asm volatile("ldmatrix.sync.aligned.m8n8.x4.shared.b16 {%0,%1,%2,%3}, [%4];"
        : "=r"(r[0]), "=r"(r[1]), "=r"(r[2]), "=r"(r[3]) : "r"(addr));
}
__device__ __forceinline__ void mma_bf16(float* c, const uint32_t* a, uint32_t b0, uint32_t b1) {
    asm volatile(
        "mma.sync.aligned.m16n8k16.row.col.f32.bf16.bf16.f32 "
        "{%0,%1,%2,%3}, {%4,%5,%6,%7}, {%8,%9}, {%0,%1,%2,%3};"
        : "+f"(c[0]), "+f"(c[1]), "+f"(c[2]), "+f"(c[3])
        : "r"(a[0]), "r"(a[1]), "r"(a[2]), "r"(a[3]), "r"(b0), "r"(b1));
}
__device__ __forceinline__ void mma_f16(float* c, const uint32_t* a, uint32_t b0, uint32_t b1) {
    asm volatile(
        "mma.sync.aligned.m16n8k16.row.col.f32.f16.f16.f32 "
        "{%0,%1,%2,%3}, {%4,%5,%6,%7}, {%8,%9}, {%0,%1,%2,%3};"
        : "+f"(c[0]), "+f"(c[1]), "+f"(c[2]), "+f"(c[3])
        : "r"(a[0]), "r"(a[1]), "r"(a[2]), "r"(a[3]), "r"(b0), "r"(b1));
}
#define CP_ASYNC16(dst, src) \
    asm volatile("cp.async.cg.shared.global [%0], [%1], 16;" :: "r"(dst), "l"(src))
#define CP_COMMIT() asm volatile("cp.async.commit_group;" ::: "memory")
#define CP_WAIT1()  asm volatile("cp.async.wait_group 1;" ::: "memory")
#define CP_WAIT0()  asm volatile("cp.async.wait_group 0;" ::: "memory")

__device__ __forceinline__ void st_bf2(__nv_bfloat16* p, __nv_bfloat16 a, __nv_bfloat16 b) {
    __nv_bfloat162 t; t.x = a; t.y = b;
    *(__nv_bfloat162*)p = t;
}
__device__ __forceinline__ uint32_t pack_h2(float a, float b) {
    __half2 t = __floats2half2_rn(a, b);
    return *(uint32_t*)&t;
}

// ---------------------------------------------------------------------------
// Split-bf16 conversion kernels (inputs + weights)
// ---------------------------------------------------------------------------
__device__ __forceinline__ void split_write(__nv_bfloat16* out, size_t o, float v, int patB) {
    __nv_bfloat16 hi = __float2bfloat16(v);
    __nv_bfloat16 lo = __float2bfloat16(v - __bfloat162float(hi));
    if (patB) { out[o] = hi; out[o + 1024] = lo; out[o + 2048] = hi; }
    else      { out[o] = hi; out[o + 1024] = hi; out[o + 2048] = lo; }
}

__global__ void split_inputs_kernel(const float* __restrict__ x, const float* __restrict__ y) {
    int idx = blockIdx.x * blockDim.x + threadIdx.x;
    const float* in = blockIdx.z ? x : y;
    __nv_bfloat16* out = blockIdx.z ? g_A2x : g_A2y;
    int r = idx >> 10, c = idx & 1023;
    split_write(out, (size_t)r * KEFF + c, in[idx], 0);
}

__global__ void split_w_kernel(const float* __restrict__ Wq, const float* __restrict__ Wk,
                               const float* __restrict__ Wv, const float* __restrict__ Wo) {
    int idx = blockIdx.x * blockDim.x + threadIdx.x;
    const float* in = blockIdx.z == 0 ? Wq : blockIdx.z == 1 ? Wk : blockIdx.z == 2 ? Wv : Wo;
    __nv_bfloat16* out = blockIdx.z == 0 ? g_W2q : blockIdx.z == 1 ? g_W2k
                       : blockIdx.z == 2 ? g_W2v : g_W2o;
    float scale = (blockIdx.z == 0) ? 0.125f : 1.0f;    // fold 1/sqrt(Dh) into Wq
    int r = idx >> 10, c = idx & 1023;
    split_write(out, (size_t)r * KEFF + c, in[idx] * scale, 1);
}

// ---------------------------------------------------------------------------
// HMMA GEMM (split-bf16, 3-stage cp.async pipeline).
// out_mode: 0=Q fp16, 1=K fp16, 2=V fp16 transposed, 3=fp32 row-major
// ---------------------------------------------------------------------------
#define GSMEM_BYTES (6 * 16384)

__device__ __forceinline__ void load_slab(const __nv_bfloat16* A, const __nv_bfloat16* Bw,
                                          uint32_t sb, int m0, int n0, int s, int buf) {
    const int tid = threadIdx.x;
    const int k0 = s * KSLAB;
    const uint32_t abase = sb + buf * 32768;
    const uint32_t bbase = abase + 16384;
    #pragma unroll
    for (int t = 0; t < 4; t++) {
        int id = tid + t * 256;
        int r = id >> 3, cb = (id & 7) * 16;
        const char* ga = (const char*)A + ((size_t)(m0 + r) * KEFF + k0) * 2 + cb;
        const char* gb = (const char*)Bw + ((size_t)(n0 + r) * KEFF + k0) * 2 + cb;
        CP_ASYNC16(abase + SWZ(r * 128 + cb), ga);
        CP_ASYNC16(bbase + SWZ(r * 128 + cb), gb);
    }
    CP_COMMIT();
}

__device__ __forceinline__ void gemm_core(const __nv_bfloat16* __restrict__ A,
                                          const __nv_bfloat16* __restrict__ Bw,
                                          float* __restrict__ out, int out_mode) {
    extern __shared__ char smem[];
    const uint32_t sb = smem_u32(smem);
    const int tid = threadIdx.x, lane = tid & 31, warp = tid >> 5;
    const int wm = (warp & 3) * 32;
    const int wn = (warp >> 2) * 64;
    const int m0 = blockIdx.y * 128, n0 = blockIdx.x * 128;

    float acc[2][8][4];
    #pragma unroll
    for (int i = 0; i < 2; i++)
        #pragma unroll
        for (int j = 0; j < 8; j++)
            #pragma unroll
            for (int q = 0; q < 4; q++) acc[i][j][q] = 0.f;

    load_slab(A, Bw, sb, m0, n0, 0, 0);
    load_slab(A, Bw, sb, m0, n0, 1, 1);

    const int lrow = lane & 15;
    const int lk16 = (lane >> 4) * 16;

    int buf = 0;
    for (int s = 0; s < NSLAB; s++) {
        if (s + 1 < NSLAB) CP_WAIT1(); else CP_WAIT0();
        __syncthreads();
        if (s + 2 < NSLAB) {
            int nbuf = buf + 2; if (nbuf >= 3) nbuf -= 3;
            load_slab(A, Bw, sb, m0, n0, s + 2, nbuf);
        }
        const uint32_t abase = sb + buf * 32768;
        const uint32_t bbase = abase + 16384;

        #pragma unroll
        for (int kk = 0; kk < 4; kk++) {
            const int kb = kk * 32;
            uint32_t a_r[2][4], b_r[4][4];
            #pragma unroll
            for (int mi = 0; mi < 2; mi++)
                ldsm_x4(a_r[mi], abase + SWZ((wm + mi * 16 + lrow) * 128 + kb + lk16));
            #pragma unroll
            for (int nj = 0; nj < 4; nj++)
                ldsm_x4(b_r[nj], bbase + SWZ((wn + nj * 16 + lrow) * 128 + kb + lk16));
            #pragma unroll
            for (int mi = 0; mi < 2; mi++)
                #pragma unroll
                for (int nj = 0; nj < 4; nj++) {
                    mma_bf16(acc[mi][nj * 2],     a_r[mi], b_r[nj][0], b_r[nj][2]);
                    mma_bf16(acc[mi][nj * 2 + 1], a_r[mi], b_r[nj][1], b_r[nj][3]);
                }
        }
        buf++; if (buf >= 3) buf = 0;
    }

    #pragma unroll
    for (int mi = 0; mi < 2; mi++)
        #pragma unroll
        for (int nj = 0; nj < 8; nj++) {
            #pragma unroll
            for (int half = 0; half < 2; half++) {
                int m = m0 + wm + mi * 16 + (lane >> 2) + half * 8;
                int n = n0 + wn + nj * 8 + (lane & 3) * 2;
                float v0 = acc[mi][nj][half * 2], v1 = acc[mi][nj][half * 2 + 1];
                if (out_mode == 3) {
                    out[(size_t)m * D_MODEL + n] = v0;
                    out[(size_t)m * D_MODEL + n + 1] = v1;
                } else {
                    int b = m >> 11, sq = m & (SEQ - 1);
                    int h = n >> 6, d = n & (HEAD_DIM - 1);
                    if (out_mode == 2) {   // V transposed [B,H,Dh,S], fp16
                        size_t o0 = ((size_t)(b * NUM_HEADS + h) * HEAD_DIM + d) * SEQ + sq;
                        g_Vf[o0] = __float2half(v0);
                        g_Vf[o0 + SEQ] = __float2half(v1);
                    } else {               // Q/K [B,H,S,Dh], fp16
                        size_t o = (((size_t)b * NUM_HEADS + h) * SEQ + sq) * HEAD_DIM + d;
                        __half2 t = __floats2half2_rn(v0, v1);
                        __half* dst = (out_mode == 0) ? g_Qf : g_Kf;
                        *(__half2*)&dst[o] = t;
                    }
                }
            }
        }
}

__global__ __launch_bounds__(256) void gemm_qkv_kernel() {
    const __nv_bfloat16* A = blockIdx.z == 0 ? g_A2y : g_A2x;
    const __nv_bfloat16* Bw = blockIdx.z == 0 ? g_W2q : blockIdx.z == 1 ? g_W2k : g_W2v;
    gemm_core(A, Bw, nullptr, (int)blockIdx.z);
}

__global__ __launch_bounds__(256) void gemm_proj_kernel(float* __restrict__ out) {
    gemm_core(g_C2, g_W2o, out, 3);
}

// ---------------------------------------------------------------------------
// HMMA attention v3: single-pass fp16, P in registers, Q frags hoisted,
// double-buffered K and V (2 syncs/chunk).
// 512 threads / 16 warps = 8 q-groups (m16) x 2 kv-groups (64 kv each).
// smem: Q 16K | K0 16K | K1 16K | V0 16K | V1 16K | rsm 1K
// ---------------------------------------------------------------------------
#define oQ  0
#define oK0 16384
#define oV0 49152
#define oRS 81920
#define ASMEM_BYTES (81920 + 1024)
#define NC (SEQ / 128)

__global__ __launch_bounds__(512, 1)
void attn_hmma_kernel(const float* __restrict__ mask)
{
    extern __shared__ char smem[];
    const uint32_t sb = smem_u32(smem);
    const int tid = threadIdx.x, lane = tid & 31, warp = tid >> 5;
    const int wm = (warp & 7) * 16;        // q offset (16 rows per warp)
    const int g  = warp >> 3;              // kv-group 0/1
    const int wn = g * 64;                 // kv offset within chunk
    const int lrow = lane & 15;
    const int lk16 = (lane >> 4) * 16;

    const int bh = blockIdx.y;
    const int b = bh >> 4, h = bh & 15;
    const int q0 = blockIdx.x * 128;

    const char* Qp = (const char*)g_Qf + (size_t)bh * SEQ * HEAD_DIM * 2;
    const char* Kp = (const char*)g_Kf + (size_t)bh * SEQ * HEAD_DIM * 2;
    const char* Vp = (const char*)g_Vf + (size_t)bh * HEAD_DIM * SEQ * 2;

    // ---- prologue: load Q + K0 (group), then V0 (group) ----
    #pragma unroll
    for (int t = 0; t < 2; t++) {
        int id = tid + t * 512;
        int r = id >> 3, cb = (id & 7) * 16;
        uint32_t so = SWZ(r * 128 + cb);
        CP_ASYNC16(sb + oQ + so, Qp + (size_t)(q0 + r) * 128 + cb);
        CP_ASYNC16(sb + oK0 + so, Kp + (size_t)r * 128 + cb);
    }
    CP_COMMIT();
    {
        int id = tid;
        int r = id >> 4, cb = (id & 15) * 16;
        uint32_t so = SWZ256(r * 256 + cb);
        CP_ASYNC16(sb + oV0 + so, Vp + (size_t)r * (SEQ * 2) + cb);
        id = tid + 512;
        r = id >> 4; cb = (id & 15) * 16;
        so = SWZ256(r * 256 + cb);
        CP_ASYNC16(sb + oV0 + so, Vp + (size_t)r * (SEQ * 2) + cb);
    }
    CP_COMMIT();

    CP_WAIT1();            // Q + K0 ready
    __syncthreads();

    // ---- hoist Q fragments (fp16, 4 k16 blocks) ----
    uint32_t qf[4][4];
    #pragma unroll
    for (int kk = 0; kk < 4; kk++)
        ldsm_x4(qf[kk], sb + oQ + SWZ((wm + lrow) * 128 + kk * 32 + lk16));

    float rs[2] = {0.f, 0.f};
    float oacc[8][4];
    #pragma unroll
    for (int j = 0; j < 8; j++)
        #pragma unroll
        for (int q = 0; q < 4; q++) oacc[j][q] = 0.f;

    const int mrow = q0 + wm + (lane >> 2);
    const int mcol0 = wn + (lane & 3) * 2;

    for (int c = 0; c < NC; c++) {
        const int kv0 = c * 128;
        const uint32_t kbase = sb + oK0 + (c & 1) * 16384;
        const uint32_t vbase = sb + oV0 + (c & 1) * 16384;

        if (c > 0) {       // K[c] ready (pending: V[c])
            CP_WAIT1();
            __syncthreads();
        }

        // ---- S = Q K^T (fp16 single-pass), warp tile 16q x 64kv ----
        float sacc[8][4];
        #pragma unroll
        for (int j = 0; j < 8; j++)
            #pragma unroll
            for (int q = 0; q < 4; q++) sacc[j][q] = 0.f;

        #pragma unroll
        for (int kk = 0; kk < 4; kk++) {
            const int kb = kk * 32;
            #pragma unroll
            for (int njg = 0; njg < 4; njg++) {
                uint32_t kh[4];
                ldsm_x4(kh, kbase + SWZ((wn + njg * 16 + lrow) * 128 + kb + lk16));
                mma_f16(sacc[njg * 2],     qf[kk], kh[0], kh[2]);
                mma_f16(sacc[njg * 2 + 1], qf[kk], kh[1], kh[3]);
            }
        }

        // prefetch K[c+1] into the other K buffer (safe: all warps past
        // top-of-chunk sync, so reads of that buffer (chunk c-1) are done)
        if (c + 1 < NC) {
            const int kvn = (c + 1) * 128;
            const uint32_t knext = sb + oK0 + ((c + 1) & 1) * 16384;
            #pragma unroll
            for (int t = 0; t < 2; t++) {
                int id = tid + t * 512;
                int r = id >> 3, cb = (id & 7) * 16;
                CP_ASYNC16(knext + SWZ(r * 128 + cb), Kp + (size_t)(kvn + r) * 128 + cb);
            }
            CP_COMMIT();
        }

        // ---- softmax: mask + exp (in regs), rowsum ----
        #pragma unroll
        for (int nj = 0; nj < 8; nj++)
            #pragma unroll
            for (int half = 0; half < 2; half++) {
                float2 mk = *(const float2*)&mask[(size_t)(mrow + half * 8) * SEQ + kv0 + mcol0 + nj * 8];
                float e0 = __expf(sacc[nj][half * 2]     + mk.x);
                float e1 = __expf(sacc[nj][half * 2 + 1] + mk.y);
                rs[half] += e0 + e1;
                sacc[nj][half * 2]     = e0;
                sacc[nj][half * 2 + 1] = e1;
            }

        if (c + 1 < NC) CP_WAIT1(); else CP_WAIT0();   // V[c] ready
        __syncthreads();

        // ---- partial PV (fp16): P from registers (C-frag -> A-frag) ----
        #pragma unroll
        for (int kk2 = 0; kk2 < 4; kk2++) {
            uint32_t ap[4];
            {
                const float* s0 = sacc[kk2 * 2];
                const float* s1 = sacc[kk2 * 2 + 1];
                ap[0] = pack_h2(s0[0], s0[1]);
                ap[1] = pack_h2(s0[2], s0[3]);
                ap[2] = pack_h2(s1[0], s1[1]);
                ap[3] = pack_h2(s1[2], s1[3]);
            }
            const int kbyte = wn * 2 + kk2 * 32;   // kv byte offset in V^T row
            #pragma unroll
            for (int dg = 0; dg < 4; dg++) {
                uint32_t vh[4];
                ldsm_x4(vh, vbase + SWZ256((dg * 16 + lrow) * 256 + kbyte + lk16));
                mma_f16(oacc[dg * 2],     ap, vh[0], vh[2]);
                mma_f16(oacc[dg * 2 + 1], ap, vh[1], vh[3]);
            }
        }

        // prefetch V[c+1] (safe: all warps past the post-V-wait sync)
        if (c + 1 < NC) {
            const int kvn = (c + 1) * 128;
            const uint32_t vnext = sb + oV0 + ((c + 1) & 1) * 16384;
            #pragma unroll
            for (int t = 0; t < 2; t++) {
                int id = tid + t * 512;
                int r = id >> 4, cb = (id & 15) * 16;
                CP_ASYNC16(vnext + SWZ256(r * 256 + cb),
                           Vp + (size_t)r * (SEQ * 2) + kvn * 2 + cb);
            }
            CP_COMMIT();
        }
    }

    // ---- rowsum: quad butterfly, per-group partials ----
    #pragma unroll
    for (int i = 0; i < 2; i++) {
        rs[i] += __shfl_xor_sync(0xffffffffu, rs[i], 1);
        rs[i] += __shfl_xor_sync(0xffffffffu, rs[i], 2);
    }
    float* rsm = (float*)(smem + oRS);   // [2][128]
    if ((lane & 3) == 0) {
        #pragma unroll
        for (int half = 0; half < 2; half++)
            rsm[g * 128 + wm + (lane >> 2) + half * 8] = rs[half];
    }

    // ---- cross-kv-group reduction (scratch over dead K buffers) ----
    const int wmw = warp & 7;
    float* scr = (float*)(smem + oK0 + wmw * 4096);   // 16x64 fp32 per q-warp
    __syncthreads();   // all reads of K/V buffers done before reuse
    if (g == 1) {
        #pragma unroll
        for (int nj = 0; nj < 8; nj++)
            #pragma unroll
            for (int half = 0; half < 2; half++) {
                int rl = (lane >> 2) + half * 8;
                int dc = nj * 8 + (lane & 3) * 2;
                *(float2*)&scr[rl * 64 + dc] = *(float2*)&oacc[nj][half * 2];
            }
    }
    __syncthreads();

    if (g == 0) {
        #pragma unroll
        for (int nj = 0; nj < 8; nj++)
            #pragma unroll
            for (int half = 0; half < 2; half++) {
                int rl = (lane >> 2) + half * 8;
                int dc = nj * 8 + (lane & 3) * 2;
                float2 part = *(float2*)&scr[rl * 64 + dc];
                int row = wm + rl;
                float inv = 1.f / (rsm[row] + rsm[128 + row] + 1e-10f);
                float v0 = (oacc[nj][half * 2]     + part.x) * inv;
                float v1 = (oacc[nj][half * 2 + 1] + part.y) * inv;
                __nv_bfloat16 h0 = __float2bfloat16(v0);
                __nv_bfloat16 l0 = __float2bfloat16(v0 - __bfloat162float(h0));
                __nv_bfloat16 h1 = __float2bfloat16(v1);
                __nv_bfloat16 l1 = __float2bfloat16(v1 - __bfloat162float(h1));
                size_t o = (size_t)(b * SEQ + q0 + row) * KEFF + h * HEAD_DIM + dc;
                st_bf2(&g_C2[o], h0, h1);
                st_bf2(&g_C2[o + 1024], h0, h1);
                st_bf2(&g_C2[o + 2048], l0, l1);
            }
    }
}

// ---------------------------------------------------------------------------
// Launch
// ---------------------------------------------------------------------------
extern "C" void kernel_launch(void* const* d_in, const int* in_sizes, int n_in,
                              void* d_out, int out_size)
{
    (void)in_sizes; (void)n_in; (void)out_size;
    const float* x    = (const float*)d_in[0];
    const float* y    = (const float*)d_in[1];
    const float* mask = (const float*)d_in[2];
    const float* Wq   = (const float*)d_in[3];
    const float* Wk   = (const float*)d_in[4];
    const float* Wv   = (const float*)d_in[5];
    const float* Wo   = (const float*)d_in[6];
    float* out = (float*)d_out;

    cudaFuncSetAttribute(gemm_qkv_kernel, cudaFuncAttributeMaxDynamicSharedMemorySize, GSMEM_BYTES);
    cudaFuncSetAttribute(gemm_proj_kernel, cudaFuncAttributeMaxDynamicSharedMemorySize, GSMEM_BYTES);
    cudaFuncSetAttribute(attn_hmma_kernel, cudaFuncAttributeMaxDynamicSharedMemorySize, ASMEM_BYTES);

    // 1) split conversions
    {
        dim3 g((NROWS * 1024) / 256, 1, 2);
        split_inputs_kernel<<<g, 256>>>(x, y);
        dim3 gw((1024 * 1024) / 256, 1, 4);
        split_w_kernel<<<gw, 256>>>(Wq, Wk, Wv, Wo);
    }
    // 2) QKV projections (split-bf16 HMMA) -> fp16 Q/K/V
    {
        dim3 g(D_MODEL / 128, NROWS / 128, 3);
        gemm_qkv_kernel<<<g, 256, GSMEM_BYTES>>>();
    }
    // 3) Attention (fp16 single-pass HMMA) -> split ctx
    {
        dim3 g(SEQ / 128, BATCH * NUM_HEADS);
        attn_hmma_kernel<<<g, 512, ASMEM_BYTES>>>(mask);
    }
    // 4) Output projection (split-bf16 HMMA)
    {
        dim3 g(D_MODEL / 128, NROWS / 128);
        gemm_proj_kernel<<<g, 256, GSMEM_BYTES>>>(out);
    }
}